// round 9
// baseline (speedup 1.0000x reference)
#include <cuda_runtime.h>
#include <math.h>
#include <stdint.h>

// Problem constants
#define BB   16
#define CC   128
#define HH   64
#define WW   64
#define HR   32
#define WR   32
#define LL   1024          // HR*WR
#define KK   1152          // CC*9

// ---------------- scratch (device globals; no allocations allowed) ------------
// NOTE: these symbols are referenced ONLY from device code. Host code passing a
// __device__ symbol as a kernel arg yields a bogus address (round<=6 bug).
__device__ float g_ft  [BB * HR * WR * CC];          // f downsampled, channel-last
__device__ float g_bt  [BB * HR * WR * CC];          // b downsampled, channel-last
__device__ float g_bot [BB * HH * WW * CC];          // b_o full-res, channel-last
__device__ float g_bnorm[BB * LL];
__device__ float g_valid[BB * LL];
__device__ float g_fg [BB * LL * KK];
__device__ float g_bsn[BB * LL * KK];
__device__ float g_bi [BB * LL * KK];
__device__ float g_S  [BB * LL * LL];                // raw S -> fused S
__device__ float g_Sf [BB * LL * LL];                // fuse stage 1 -> score
__device__ float g_R  [BB * LL * KK];

// ---------------- transpose to channel-last ----------------------------------
// dst[b][y][x][c] = src[b][c][2y][2x]   (32x32 downsampled), sel: 0 -> g_ft, 1 -> g_bt
__global__ void k_trans_ds(const float* __restrict__ src, int sel) {
    __shared__ float stage[HR * 129];   // [x][c] padded
    const int y = blockIdx.x;
    const int b = blockIdx.y;
    float* dst = sel ? g_bt : g_ft;
    const int tid = threadIdx.x;
    for (int i = tid; i < HR * CC; i += 256) {
        int x = i & 31;
        int c = i >> 5;
        stage[x * 129 + c] = src[(((size_t)b * CC + c) * HH + 2 * y) * WW + 2 * x];
    }
    __syncthreads();
    for (int i = tid; i < HR * CC; i += 256) {
        int c = i & 127;
        int x = i >> 7;
        dst[(((size_t)b * HR + y) * WR + x) * CC + c] = stage[x * 129 + c];
    }
}

// g_bot[b][y][x][c] = b_o[b][c][y][x]  (64x64 full-res)
__global__ void k_trans_full(const float* __restrict__ src) {
    __shared__ float stage[WW * 129];
    const int y = blockIdx.x;
    const int b = blockIdx.y;
    const int tid = threadIdx.x;
    for (int i = tid; i < WW * CC; i += 256) {
        int x = i & 63;
        int c = i >> 6;
        stage[x * 129 + c] = src[(((size_t)b * CC + c) * HH + y) * WW + x];
    }
    __syncthreads();
    for (int i = tid; i < WW * CC; i += 256) {
        int c = i & 127;
        int x = i >> 7;
        g_bot[(((size_t)b * HH + y) * WW + x) * CC + c] = stage[x * 129 + c];
    }
}

// ---------------- bnorm -------------------------------------------------------
__global__ void k_bnorm() {
    __shared__ float ss[LL];
    const int b = blockIdx.x;
    const int tid = threadIdx.x;
    const int warp = tid >> 5, lane = tid & 31;
    for (int pos = warp; pos < LL; pos += 32) {
        float4 v = *(const float4*)&g_bt[((size_t)b * LL + pos) * CC + lane * 4];
        float s = v.x * v.x + v.y * v.y + v.z * v.z + v.w * v.w;
        #pragma unroll
        for (int o = 16; o; o >>= 1) s += __shfl_xor_sync(0xffffffffu, s, o);
        if (lane == 0) ss[pos] = s;
    }
    __syncthreads();
    const int p = tid, py = p >> 5, px = p & 31;
    float sum = 0.f;
    #pragma unroll
    for (int i = 0; i < 3; i++)
        #pragma unroll
        for (int j = 0; j < 3; j++) {
            int y = py + i - 1, x = px + j - 1;
            if ((unsigned)y < HR && (unsigned)x < WR) sum += ss[y * WR + x];
        }
    g_bnorm[b * LL + p] = fmaxf(sqrtf(sum), 1e-4f);
}

// ---------------- valid mask --------------------------------------------------
__global__ void k_valid(const float* __restrict__ mask_o) {
    __shared__ float md[LL];
    const int b = blockIdx.x;
    const int tid = threadIdx.x;
    md[tid] = mask_o[(size_t)b * HH * WW + (2 * (tid >> 5)) * WW + 2 * (tid & 31)];
    __syncthreads();
    const int py = tid >> 5, px = tid & 31;
    float sum = 0.f;
    #pragma unroll
    for (int i = 0; i < 3; i++)
        #pragma unroll
        for (int j = 0; j < 3; j++) {
            int y = py + i - 1, x = px + j - 1;
            if ((unsigned)y < HR && (unsigned)x < WR) sum += md[y * WR + x];
        }
    g_valid[b * LL + tid] = (sum == 0.f) ? 1.f : 0.f;
}

// ---------------- patch matrices ---------------------------------------------
__global__ void k_patches() {
    const int p = blockIdx.x;
    const int b = blockIdx.y;
    const int c = threadIdx.x;
    const int py = p >> 5, px = p & 31;
    const float nrm = g_bnorm[b * LL + p];
    const size_t base = ((size_t)b * LL + p) * KK;
    #pragma unroll
    for (int ij = 0; ij < 9; ij++) {
        const int i = ij / 3, j = ij % 3;
        const int y = py + i - 1, x = px + j - 1;
        float fv = 0.f, bv = 0.f;
        if ((unsigned)y < HR && (unsigned)x < WR) {
            size_t o = (((size_t)b * HR + y) * WR + x) * CC + c;
            fv = g_ft[o];
            bv = g_bt[o];
        }
        g_fg [base + ij * CC + c] = fv;
        g_bsn[base + ij * CC + c] = bv / nrm;
        const int yy = 2 * py + i - 1, xx = 2 * px + j - 1;
        float biv = 0.f;
        if ((unsigned)yy < HH && (unsigned)xx < WW)
            biv = g_bot[(((size_t)b * HH + yy) * WW + xx) * CC + c];
        g_bi[base + ij * CC + c] = biv;
    }
}

// ---------------- GEMM1 (NT): S[p][q] = sum_k bsn[p][k] * fg[q][k] -------------
// M = N = LL, K = KK; operands bound to device globals inside device code.
__global__ void __launch_bounds__(256) k_gemm1() {
    __shared__ float As[8][128];
    __shared__ float Bs[8][128];
    const int b = blockIdx.z;
    const float* Ab = g_bsn + (size_t)b * LL * KK;
    const float* Bb = g_fg  + (size_t)b * LL * KK;
    float*       Cb = g_S   + (size_t)b * LL * LL;
    const int m0 = blockIdx.y * 128;
    const int n0 = blockIdx.x * 128;
    const int tid = threadIdx.x;
    const int tx = tid & 15, ty = tid >> 4;
    const int ar = tid >> 1;
    const int ac = (tid & 1) << 2;
    float acc[8][8];
    #pragma unroll
    for (int i = 0; i < 8; i++)
        #pragma unroll
        for (int j = 0; j < 8; j++) acc[i][j] = 0.f;
    for (int kt = 0; kt < KK; kt += 8) {
        float4 av = *(const float4*)(Ab + (size_t)(m0 + ar) * KK + kt + ac);
        float4 bv = *(const float4*)(Bb + (size_t)(n0 + ar) * KK + kt + ac);
        As[ac + 0][ar] = av.x; As[ac + 1][ar] = av.y;
        As[ac + 2][ar] = av.z; As[ac + 3][ar] = av.w;
        Bs[ac + 0][ar] = bv.x; Bs[ac + 1][ar] = bv.y;
        Bs[ac + 2][ar] = bv.z; Bs[ac + 3][ar] = bv.w;
        __syncthreads();
        #pragma unroll
        for (int kk = 0; kk < 8; kk++) {
            float a[8], bb[8];
            #pragma unroll
            for (int i = 0; i < 8; i++) a[i] = As[kk][ty * 8 + i];
            #pragma unroll
            for (int j = 0; j < 8; j++) bb[j] = Bs[kk][tx * 8 + j];
            #pragma unroll
            for (int i = 0; i < 8; i++)
                #pragma unroll
                for (int j = 0; j < 8; j++) acc[i][j] += a[i] * bb[j];
        }
        __syncthreads();
    }
    #pragma unroll
    for (int i = 0; i < 8; i++) {
        float* crow = Cb + (size_t)(m0 + ty * 8 + i) * LL + n0 + tx * 8;
        *(float4*)(crow)     = make_float4(acc[i][0], acc[i][1], acc[i][2], acc[i][3]);
        *(float4*)(crow + 4) = make_float4(acc[i][4], acc[i][5], acc[i][6], acc[i][7]);
    }
}

// ---------------- GEMM2 (TN): R[q][k'] = sum_p score[p][q] * bi[p][k'] ---------
// A = g_Sf (score, K x M = LL x LL), B = g_bi (K x N = LL x KK), C = g_R.
__global__ void __launch_bounds__(256) k_gemm2() {
    __shared__ float As[8][128];
    __shared__ float Bs[8][128];
    const int b = blockIdx.z;
    const float* Ab = g_Sf + (size_t)b * LL * LL;
    const float* Bb = g_bi + (size_t)b * LL * KK;
    float*       Cb = g_R  + (size_t)b * LL * KK;
    const int m0 = blockIdx.y * 128;
    const int n0 = blockIdx.x * 128;
    const int tid = threadIdx.x;
    const int tx = tid & 15, ty = tid >> 4;
    const int lk = tid >> 5;
    const int lm = (tid & 31) << 2;
    float acc[8][8];
    #pragma unroll
    for (int i = 0; i < 8; i++)
        #pragma unroll
        for (int j = 0; j < 8; j++) acc[i][j] = 0.f;
    for (int kt = 0; kt < LL; kt += 8) {
        float4 av = *(const float4*)(Ab + (size_t)(kt + lk) * LL + m0 + lm);
        float4 bv = *(const float4*)(Bb + (size_t)(kt + lk) * KK + n0 + lm);
        *(float4*)&As[lk][lm] = av;
        *(float4*)&Bs[lk][lm] = bv;
        __syncthreads();
        #pragma unroll
        for (int kk = 0; kk < 8; kk++) {
            float a[8], bb[8];
            #pragma unroll
            for (int i = 0; i < 8; i++) a[i] = As[kk][ty * 8 + i];
            #pragma unroll
            for (int j = 0; j < 8; j++) bb[j] = Bs[kk][tx * 8 + j];
            #pragma unroll
            for (int i = 0; i < 8; i++)
                #pragma unroll
                for (int j = 0; j < 8; j++) acc[i][j] += a[i] * bb[j];
        }
        __syncthreads();
    }
    #pragma unroll
    for (int i = 0; i < 8; i++) {
        float* crow = Cb + (size_t)(m0 + ty * 8 + i) * KK + n0 + tx * 8;
        *(float4*)(crow)     = make_float4(acc[i][0], acc[i][1], acc[i][2], acc[i][3]);
        *(float4*)(crow + 4) = make_float4(acc[i][4], acc[i][5], acc[i][6], acc[i][7]);
    }
}

// ---------------- fuse: two literal diag-fuse passes with folded transpose ----
// tsw: flat-index transpose of the 32x32 structure (self-inverse since hr==wr)
__device__ __forceinline__ int tsw(int x) { return ((x & 31) << 5) | (x >> 5); }

// dst[p,q] = sum_{d=-1..1} src[tsw(p)+d, tsw(q)+d]   (flat-index bounds [0,L))
// stage 0: src=g_S (raw),  dst=g_Sf
// stage 1: src=g_Sf,       dst=g_S  (= reference fused output)
__global__ void k_fuse_pass(int stage) {
    const int b = blockIdx.z;
    const int p = blockIdx.y;
    const int q = blockIdx.x * 256 + threadIdx.x;
    const float* src = stage ? g_Sf : g_S;
    float*       dst = stage ? g_S  : g_Sf;
    const float* Sb = src + ((size_t)b << 20);
    const int tp = tsw(p), tq = tsw(q);
    float acc = 0.f;
    #pragma unroll
    for (int d = -1; d <= 1; d++) {
        const int a = tp + d, c2 = tq + d;
        if ((unsigned)a < LL && (unsigned)c2 < LL)
            acc += Sb[((size_t)a << 10) + c2];
    }
    dst[((size_t)b << 20) + ((size_t)p << 10) + q] = acc;
}

// ---------------- softmax over p per (b,q); reads g_S, writes score to g_Sf ---
__global__ void k_softmax() {
    __shared__ float sval[LL];
    const int b = blockIdx.y;
    const int q = blockIdx.x * 256 + threadIdx.x;
    for (int i = threadIdx.x; i < LL; i += 256) sval[i] = g_valid[b * LL + i];
    __syncthreads();
    const float* Sf = g_S + ((size_t)b << 20);
    float* Sc = g_Sf + ((size_t)b << 20);
    float mx = -1e30f;
    for (int p = 0; p < LL; p++) {
        float v = Sf[((size_t)p << 10) + q] * sval[p] * 10.f;
        mx = fmaxf(mx, v);
    }
    float sum = 0.f;
    for (int p = 0; p < LL; p++) {
        float v = Sf[((size_t)p << 10) + q] * sval[p] * 10.f;
        sum += expf(v - mx);
    }
    const float inv = 1.f / sum;
    for (int p = 0; p < LL; p++) {
        float v = Sf[((size_t)p << 10) + q] * sval[p] * 10.f;
        Sc[((size_t)p << 10) + q] = expf(v - mx) * inv * sval[p];
    }
}

// ---------------- transposed-conv gather from R -------------------------------
__global__ void k_out(float* __restrict__ out) {
    const int y = blockIdx.x;
    const int b = blockIdx.y;
    const int c = threadIdx.x;
    int qylo = (y - 1) < 0 ? 0 : (y - 1) >> 1;
    int qyhi = (y + 1) >> 1; if (qyhi > 31) qyhi = 31;
    for (int x = 0; x < WW; x++) {
        int qxlo = (x - 1) < 0 ? 0 : (x - 1) >> 1;
        int qxhi = (x + 1) >> 1; if (qxhi > 31) qxhi = 31;
        float acc = 0.f;
        for (int qy = qylo; qy <= qyhi; qy++) {
            const int i = y - 2 * qy + 1;
            if (i < 0 || i > 2) continue;
            for (int qx = qxlo; qx <= qxhi; qx++) {
                const int j = x - 2 * qx + 1;
                if (j < 0 || j > 2) continue;
                const int q = qy * WR + qx;
                acc += g_R[(((size_t)b * LL + q) * 9 + i * 3 + j) * CC + c];
            }
        }
        out[(((size_t)b * CC + c) * HH + y) * WW + x] = acc * 0.25f;
    }
}

// ---------------- orchestration ----------------------------------------------
extern "C" void kernel_launch(void* const* d_in, const int* in_sizes, int n_in,
                              void* d_out, int out_size) {
    // Defensive input resolution: mask_o is the only input with 16*1*64*64
    // elements; the two 16*128*64*64 tensors keep their relative order (f, b).
    const float* big[2] = {nullptr, nullptr};
    const float* mask_o = nullptr;
    int nb = 0;
    for (int i = 0; i < n_in && i < 3; i++) {
        if (in_sizes[i] == BB * 1 * HH * WW) {
            mask_o = (const float*)d_in[i];
        } else if (nb < 2) {
            big[nb++] = (const float*)d_in[i];
        }
    }
    const float* f_o = big[0] ? big[0] : (const float*)d_in[0];
    const float* b_o = big[1] ? big[1] : (const float*)d_in[1];
    if (!mask_o) mask_o = (const float*)d_in[2];
    float* out = (float*)d_out;

    k_trans_ds  <<<dim3(HR, BB), 256>>>(f_o, 0);
    k_trans_ds  <<<dim3(HR, BB), 256>>>(b_o, 1);
    k_trans_full<<<dim3(HH, BB), 256>>>(b_o);
    k_bnorm     <<<BB, 1024>>>();
    k_valid     <<<BB, 1024>>>(mask_o);
    k_patches   <<<dim3(LL, BB), 128>>>();
    // S = bsn * fg^T  (per batch 1024x1024x1152) -> g_S
    k_gemm1     <<<dim3(LL / 128, LL / 128, BB), 256>>>();
    // fuse: g_S -> g_Sf -> g_S (two literal diag-fuse+transpose passes)
    k_fuse_pass <<<dim3(LL / 256, LL, BB), 256>>>(0);
    k_fuse_pass <<<dim3(LL / 256, LL, BB), 256>>>(1);
    // softmax: reads fused g_S, writes score to g_Sf
    k_softmax   <<<dim3(LL / 256, BB), 256>>>();
    // R[q][k'] = sum_p score[p][q] * bi[p][k']  (per batch 1024x1152x1024)
    k_gemm2     <<<dim3(KK / 128, LL / 128, BB), 256>>>();
    k_out       <<<dim3(HH, BB), CC>>>(out);
}

// round 11
// speedup vs baseline: 1.6770x; 1.6770x over previous
#include <cuda_runtime.h>
#include <cuda_bf16.h>
#include <math.h>
#include <stdint.h>

// Problem constants
#define BB   16
#define CC   128
#define HH   64
#define WW   64
#define HR   32
#define WR   32
#define LL   1024          // HR*WR
#define KK   1152          // CC*9

// ---------------- scratch (device globals; only referenced from device code) --
__device__ float g_ft  [BB * HR * WR * CC];
__device__ float g_bt  [BB * HR * WR * CC];
__device__ float g_bot [BB * HH * WW * CC];
__device__ float g_bnorm[BB * LL];
__device__ float g_valid[BB * LL];
__device__ float g_S  [BB * LL * LL];                // raw S -> fused S
__device__ float g_Sf [BB * LL * LL];                // fuse stage 1
__device__ float g_R  [BB * LL * KK];
// bf16 split operands (row-major, k-minor)
__device__ __nv_bfloat16 g_A1h[BB * LL * KK];        // bsn hi   [b][p][k]
__device__ __nv_bfloat16 g_A1l[BB * LL * KK];        // bsn lo
__device__ __nv_bfloat16 g_B1h[BB * LL * KK];        // fg hi    [b][q][k]
__device__ __nv_bfloat16 g_B1l[BB * LL * KK];        // fg lo
__device__ __nv_bfloat16 g_A2h[BB * LL * LL];        // score^T hi [b][q][p]
__device__ __nv_bfloat16 g_A2l[BB * LL * LL];        // score^T lo
__device__ __nv_bfloat16 g_B2h[BB * KK * LL];        // bi^T hi  [b][k'][p]
__device__ __nv_bfloat16 g_B2l[BB * KK * LL];        // bi^T lo

// ---------------- PTX helpers (all baseline sm_80+, legal on compute_103) ----
__device__ __forceinline__ uint32_t smem_u32(const void* p) {
    uint32_t a;
    asm("{ .reg .u64 t; cvta.to.shared.u64 t, %1; cvt.u32.u64 %0, t; }" : "=r"(a) : "l"(p));
    return a;
}

#define CP_ASYNC16(dst, src) \
    asm volatile("cp.async.cg.shared.global [%0], [%1], 16;" :: "r"(dst), "l"(src))
#define CP_COMMIT() asm volatile("cp.async.commit_group;" ::: "memory")
#define CP_WAIT(n)  asm volatile("cp.async.wait_group %0;" :: "n"(n) : "memory")

#define LDSM_X4(r0, r1, r2, r3, addr) \
    asm volatile("ldmatrix.sync.aligned.m8n8.x4.shared.b16 {%0,%1,%2,%3}, [%4];" \
        : "=r"(r0), "=r"(r1), "=r"(r2), "=r"(r3) : "r"(addr))

#define MMA_BF16(c, a, b0, b1) \
    asm volatile("mma.sync.aligned.m16n8k16.row.col.f32.bf16.bf16.f32 " \
        "{%0,%1,%2,%3}, {%4,%5,%6,%7}, {%8,%9}, {%0,%1,%2,%3};" \
        : "+f"((c)[0]), "+f"((c)[1]), "+f"((c)[2]), "+f"((c)[3]) \
        : "r"((a)[0]), "r"((a)[1]), "r"((a)[2]), "r"((a)[3]), "r"(b0), "r"(b1))

// ---------------- transpose to channel-last ----------------------------------
__global__ void k_trans_ds(const float* __restrict__ src, int sel) {
    __shared__ float stage[HR * 129];
    const int y = blockIdx.x;
    const int b = blockIdx.y;
    float* dst = sel ? g_bt : g_ft;
    const int tid = threadIdx.x;
    for (int i = tid; i < HR * CC; i += 256) {
        int x = i & 31;
        int c = i >> 5;
        stage[x * 129 + c] = src[(((size_t)b * CC + c) * HH + 2 * y) * WW + 2 * x];
    }
    __syncthreads();
    for (int i = tid; i < HR * CC; i += 256) {
        int c = i & 127;
        int x = i >> 7;
        dst[(((size_t)b * HR + y) * WR + x) * CC + c] = stage[x * 129 + c];
    }
}

__global__ void k_trans_full(const float* __restrict__ src) {
    __shared__ float stage[WW * 129];
    const int y = blockIdx.x;
    const int b = blockIdx.y;
    const int tid = threadIdx.x;
    for (int i = tid; i < WW * CC; i += 256) {
        int x = i & 63;
        int c = i >> 6;
        stage[x * 129 + c] = src[(((size_t)b * CC + c) * HH + y) * WW + x];
    }
    __syncthreads();
    for (int i = tid; i < WW * CC; i += 256) {
        int c = i & 127;
        int x = i >> 7;
        g_bot[(((size_t)b * HH + y) * WW + x) * CC + c] = stage[x * 129 + c];
    }
}

// ---------------- bnorm -------------------------------------------------------
__global__ void k_bnorm() {
    __shared__ float ss[LL];
    const int b = blockIdx.x;
    const int tid = threadIdx.x;
    const int warp = tid >> 5, lane = tid & 31;
    for (int pos = warp; pos < LL; pos += 32) {
        float4 v = *(const float4*)&g_bt[((size_t)b * LL + pos) * CC + lane * 4];
        float s = v.x * v.x + v.y * v.y + v.z * v.z + v.w * v.w;
        #pragma unroll
        for (int o = 16; o; o >>= 1) s += __shfl_xor_sync(0xffffffffu, s, o);
        if (lane == 0) ss[pos] = s;
    }
    __syncthreads();
    const int p = tid, py = p >> 5, px = p & 31;
    float sum = 0.f;
    #pragma unroll
    for (int i = 0; i < 3; i++)
        #pragma unroll
        for (int j = 0; j < 3; j++) {
            int y = py + i - 1, x = px + j - 1;
            if ((unsigned)y < HR && (unsigned)x < WR) sum += ss[y * WR + x];
        }
    g_bnorm[b * LL + p] = fmaxf(sqrtf(sum), 1e-4f);
}

// ---------------- valid mask --------------------------------------------------
__global__ void k_valid(const float* __restrict__ mask_o) {
    __shared__ float md[LL];
    const int b = blockIdx.x;
    const int tid = threadIdx.x;
    md[tid] = mask_o[(size_t)b * HH * WW + (2 * (tid >> 5)) * WW + 2 * (tid & 31)];
    __syncthreads();
    const int py = tid >> 5, px = tid & 31;
    float sum = 0.f;
    #pragma unroll
    for (int i = 0; i < 3; i++)
        #pragma unroll
        for (int j = 0; j < 3; j++) {
            int y = py + i - 1, x = px + j - 1;
            if ((unsigned)y < HR && (unsigned)x < WR) sum += md[y * WR + x];
        }
    g_valid[b * LL + tid] = (sum == 0.f) ? 1.f : 0.f;
}

// ---------------- patch matrices -> bf16 hi/lo planes -------------------------
__global__ void k_patches() {
    const int p = blockIdx.x;
    const int b = blockIdx.y;
    const int c = threadIdx.x;
    const int py = p >> 5, px = p & 31;
    const float nrm = g_bnorm[b * LL + p];
    const size_t rowb = ((size_t)b * LL + p) * KK;
    #pragma unroll
    for (int ij = 0; ij < 9; ij++) {
        const int i = ij / 3, j = ij % 3;
        const int y = py + i - 1, x = px + j - 1;
        float fv = 0.f, bv = 0.f;
        if ((unsigned)y < HR && (unsigned)x < WR) {
            size_t o = (((size_t)b * HR + y) * WR + x) * CC + c;
            fv = g_ft[o];
            bv = g_bt[o];
        }
        const float sv = bv / nrm;
        const size_t idx = rowb + ij * CC + c;
        __nv_bfloat16 h = __float2bfloat16(sv);
        g_A1h[idx] = h;
        g_A1l[idx] = __float2bfloat16(sv - __bfloat162float(h));
        h = __float2bfloat16(fv);
        g_B1h[idx] = h;
        g_B1l[idx] = __float2bfloat16(fv - __bfloat162float(h));
    }
}

// ---------------- bi^T planes (GEMM2 B): rows k' = ij*128+c, cols p -----------
__global__ void k_biT() {
    __shared__ float stage[64 * 129];
    const int pc = blockIdx.x;     // p chunk (0..15), 64 wide
    const int t  = blockIdx.y;     // ij (0..8)
    const int b  = blockIdx.z;
    const int i = t / 3, j = t % 3;
    const int tid = threadIdx.x;   // 256
    for (int idx = tid; idx < 8192; idx += 256) {
        int pl = idx >> 7, rr = idx & 127;   // pl: local p, rr: channel
        int p = pc * 64 + pl;
        int y = 2 * (p >> 5) + i - 1, x = 2 * (p & 31) + j - 1;
        float v = 0.f;
        if ((unsigned)y < HH && (unsigned)x < WW)
            v = g_bot[(((size_t)b * HH + y) * WW + x) * CC + rr];
        stage[pl * 129 + rr] = v;
    }
    __syncthreads();
    for (int idx = tid; idx < 8192; idx += 256) {
        int rr = idx >> 6, cc = idx & 63;    // rr: channel, cc: local p
        float v = stage[cc * 129 + rr];
        const size_t o = (((size_t)b * KK + t * 128 + rr) << 10) + pc * 64 + cc;
        __nv_bfloat16 h = __float2bfloat16(v);
        g_B2h[o] = h;
        g_B2l[o] = __float2bfloat16(v - __bfloat162float(h));
    }
}

// ---------------- mma.sync split-bf16 GEMM ------------------------------------
// sel 0: S[p][q]  = sum_k bsn[p][k]*fg[q][k]          (M=N=1024, K=1152)
// sel 1: R[q][k'] = sum_p scoreT[q][p]*biT[k'][p]     (M=1024, N=1152, K=1024)
// CTA tile 128x128, BK=32, 8 warps @ 32x64, double-buffered cp.async.
#define SM_STRIDE 40                 // padded bf16 elems per smem row
#define TILE_BYTES (128 * SM_STRIDE * 2)   // 10240
#define STAGE_BYTES (4 * TILE_BYTES)       // Ah, Al, Bh, Bl
#define K_MMA_SMEM (2 * STAGE_BYTES)       // 81920

__global__ void __launch_bounds__(256) k_mma(int sel) {
    extern __shared__ __align__(16) char smem[];
    const uint32_t sbase = smem_u32(smem);
    const int tid = threadIdx.x;
    const int lane = tid & 31, wid = tid >> 5;
    const int wm = (wid & 3) * 32;       // warp m offset in tile
    const int wn = (wid >> 2) * 64;      // warp n offset in tile
    const int b = blockIdx.z, my = blockIdx.y, nx = blockIdx.x;

    const int Kdim = sel ? LL : KK;
    const int Ncols = sel ? KK : LL;     // C row stride
    const __nv_bfloat16* Ah = sel ? g_A2h + ((size_t)b << 20) : g_A1h + (size_t)b * LL * KK;
    const __nv_bfloat16* Al = sel ? g_A2l + ((size_t)b << 20) : g_A1l + (size_t)b * LL * KK;
    const __nv_bfloat16* Bh = sel ? g_B2h + (size_t)b * KK * LL : g_B1h + (size_t)b * LL * KK;
    const __nv_bfloat16* Bl = sel ? g_B2l + (size_t)b * KK * LL : g_B1l + (size_t)b * LL * KK;
    float* Cb = sel ? g_R + (size_t)b * LL * KK : g_S + ((size_t)b << 20);

    // per-thread gmem->smem copy slots: 4 tiles x 512 16B-chunks, 8 per thread
    const int iters = Kdim / 32;

    float acc[2][8][4];
    #pragma unroll
    for (int mt = 0; mt < 2; mt++)
        #pragma unroll
        for (int nt = 0; nt < 8; nt++)
            #pragma unroll
            for (int u = 0; u < 4; u++) acc[mt][nt][u] = 0.f;

    // ---- stage loader ----
    auto load_stage = [&](int kt, int buf) {
        const uint32_t sdst = sbase + buf * STAGE_BYTES;
        #pragma unroll
        for (int t = 0; t < 4; t++) {
            const __nv_bfloat16* src = (t == 0) ? Ah : (t == 1) ? Al : (t == 2) ? Bh : Bl;
            const int rowbase = (t < 2) ? my * 128 : nx * 128;
            #pragma unroll
            for (int u = 0; u < 2; u++) {
                const int id = tid * 2 + u;             // 0..511
                const int r = id >> 2, c4 = id & 3;     // row, 16B-chunk (8 elems)
                const uint32_t d = sdst + t * TILE_BYTES + (r * SM_STRIDE + c4 * 8) * 2;
                const __nv_bfloat16* s = src + (size_t)(rowbase + r) * Kdim + kt + c4 * 8;
                CP_ASYNC16(d, s);
            }
        }
        CP_COMMIT();
    };

    load_stage(0, 0);

    for (int i = 0; i < iters; i++) {
        const int buf = i & 1;
        if (i + 1 < iters) load_stage((i + 1) * 32, buf ^ 1);
        if (i + 1 < iters) { CP_WAIT(1); } else { CP_WAIT(0); }
        __syncthreads();

        const uint32_t sa = sbase + buf * STAGE_BYTES;
        const uint32_t pAh = sa, pAl = sa + TILE_BYTES;
        const uint32_t pBh = sa + 2 * TILE_BYTES, pBl = sa + 3 * TILE_BYTES;

        #pragma unroll
        for (int ks = 0; ks < 2; ks++) {
            uint32_t ah[2][4], al[2][4];
            #pragma unroll
            for (int mt = 0; mt < 2; mt++) {
                const int r = wm + mt * 16 + (lane & 15);
                const uint32_t off = (uint32_t)(r * SM_STRIDE + ks * 16 + ((lane >> 4) << 3)) * 2;
                LDSM_X4(ah[mt][0], ah[mt][1], ah[mt][2], ah[mt][3], pAh + off);
                LDSM_X4(al[mt][0], al[mt][1], al[mt][2], al[mt][3], pAl + off);
            }
            #pragma unroll
            for (int np = 0; np < 4; np++) {
                const int rn = wn + np * 16 + (lane & 7) + ((lane >> 4) << 3);
                const uint32_t off = (uint32_t)(rn * SM_STRIDE + ks * 16 + (((lane >> 3) & 1) << 3)) * 2;
                uint32_t bh4[4], bl4[4];
                LDSM_X4(bh4[0], bh4[1], bh4[2], bh4[3], pBh + off);
                LDSM_X4(bl4[0], bl4[1], bl4[2], bl4[3], pBl + off);
                #pragma unroll
                for (int h2 = 0; h2 < 2; h2++) {
                    const int nt = np * 2 + h2;
                    #pragma unroll
                    for (int mt = 0; mt < 2; mt++) {
                        MMA_BF16(acc[mt][nt], ah[mt], bh4[h2 * 2], bh4[h2 * 2 + 1]);
                        MMA_BF16(acc[mt][nt], ah[mt], bl4[h2 * 2], bl4[h2 * 2 + 1]);
                        MMA_BF16(acc[mt][nt], al[mt], bh4[h2 * 2], bh4[h2 * 2 + 1]);
                    }
                }
            }
        }
        __syncthreads();
    }

    // ---- store C ----
    #pragma unroll
    for (int mt = 0; mt < 2; mt++) {
        const int row0 = my * 128 + wm + mt * 16 + (lane >> 2);
        #pragma unroll
        for (int nt = 0; nt < 8; nt++) {
            const int col = nx * 128 + wn + nt * 8 + (lane & 3) * 2;
            float* c0 = Cb + (size_t)row0 * Ncols + col;
            float* c1 = Cb + (size_t)(row0 + 8) * Ncols + col;
            c0[0] = acc[mt][nt][0]; c0[1] = acc[mt][nt][1];
            c1[0] = acc[mt][nt][2]; c1[1] = acc[mt][nt][3];
        }
    }
}

// ---------------- fuse: two literal diag-fuse passes with folded transpose ----
__device__ __forceinline__ int tsw(int x) { return ((x & 31) << 5) | (x >> 5); }

__global__ void k_fuse_pass(int stage) {
    const int b = blockIdx.z;
    const int p = blockIdx.y;
    const int q = blockIdx.x * 256 + threadIdx.x;
    const float* src = stage ? g_Sf : g_S;
    float*       dst = stage ? g_S  : g_Sf;
    const float* Sb = src + ((size_t)b << 20);
    const int tp = tsw(p), tq = tsw(q);
    float acc = 0.f;
    #pragma unroll
    for (int d = -1; d <= 1; d++) {
        const int a = tp + d, c2 = tq + d;
        if ((unsigned)a < LL && (unsigned)c2 < LL)
            acc += Sb[((size_t)a << 10) + c2];
    }
    dst[((size_t)b << 20) + ((size_t)p << 10) + q] = acc;
}

// ---------------- softmax over p; writes score^T hi/lo rows -------------------
__global__ void k_softmax() {
    __shared__ float sval[LL];
    __shared__ float stage[128 * 65];
    const int qt = blockIdx.x;     // 0..7
    const int b  = blockIdx.y;
    const int ql = threadIdx.x;    // 128 threads
    const int q = qt * 128 + ql;
    for (int i = ql; i < LL; i += 128) sval[i] = g_valid[b * LL + i];
    __syncthreads();
    const float* S = g_S + ((size_t)b << 20);
    float mx = -1e30f;
    for (int p = 0; p < LL; p++)
        mx = fmaxf(mx, S[((size_t)p << 10) + q] * sval[p] * 10.f);
    float sum = 0.f;
    for (int p = 0; p < LL; p++)
        sum += expf(S[((size_t)p << 10) + q] * sval[p] * 10.f - mx);
    const float inv = 1.f / sum;
    for (int pc = 0; pc < 16; pc++) {
        for (int pl = 0; pl < 64; pl++) {
            const int p = pc * 64 + pl;
            stage[ql * 65 + pl] = expf(S[((size_t)p << 10) + q] * sval[p] * 10.f - mx) * inv * sval[p];
        }
        __syncthreads();
        // write scoreT rows: row = qt*128 + rr, cols pc*64 + cc
        for (int idx = ql; idx < 8192; idx += 128) {
            const int rr = idx >> 6, cc = idx & 63;
            const float v = stage[rr * 65 + cc];
            const size_t o = (((size_t)b << 10) + qt * 128 + rr << 10) + pc * 64 + cc;
            __nv_bfloat16 h = __float2bfloat16(v);
            g_A2h[o] = h;
            g_A2l[o] = __float2bfloat16(v - __bfloat162float(h));
        }
        __syncthreads();
    }
}

// ---------------- transposed-conv gather from R -------------------------------
__global__ void k_out(float* __restrict__ out) {
    const int y = blockIdx.x;
    const int b = blockIdx.y;
    const int c = threadIdx.x;
    int qylo = (y - 1) < 0 ? 0 : (y - 1) >> 1;
    int qyhi = (y + 1) >> 1; if (qyhi > 31) qyhi = 31;
    for (int x = 0; x < WW; x++) {
        int qxlo = (x - 1) < 0 ? 0 : (x - 1) >> 1;
        int qxhi = (x + 1) >> 1; if (qxhi > 31) qxhi = 31;
        float acc = 0.f;
        for (int qy = qylo; qy <= qyhi; qy++) {
            const int i = y - 2 * qy + 1;
            if (i < 0 || i > 2) continue;
            for (int qx = qxlo; qx <= qxhi; qx++) {
                const int j = x - 2 * qx + 1;
                if (j < 0 || j > 2) continue;
                const int q = qy * WR + qx;
                acc += g_R[(((size_t)b * LL + q) * 9 + i * 3 + j) * CC + c];
            }
        }
        out[(((size_t)b * CC + c) * HH + y) * WW + x] = acc * 0.25f;
    }
}

// ---------------- orchestration ----------------------------------------------
extern "C" void kernel_launch(void* const* d_in, const int* in_sizes, int n_in,
                              void* d_out, int out_size) {
    const float* big[2] = {nullptr, nullptr};
    const float* mask_o = nullptr;
    int nb = 0;
    for (int i = 0; i < n_in && i < 3; i++) {
        if (in_sizes[i] == BB * 1 * HH * WW) {
            mask_o = (const float*)d_in[i];
        } else if (nb < 2) {
            big[nb++] = (const float*)d_in[i];
        }
    }
    const float* f_o = big[0] ? big[0] : (const float*)d_in[0];
    const float* b_o = big[1] ? big[1] : (const float*)d_in[1];
    if (!mask_o) mask_o = (const float*)d_in[2];
    float* out = (float*)d_out;

    cudaFuncSetAttribute(k_mma, cudaFuncAttributeMaxDynamicSharedMemorySize, K_MMA_SMEM);

    k_trans_ds  <<<dim3(HR, BB), 256>>>(f_o, 0);
    k_trans_ds  <<<dim3(HR, BB), 256>>>(b_o, 1);
    k_trans_full<<<dim3(HH, BB), 256>>>(b_o);
    k_bnorm     <<<BB, 1024>>>();
    k_valid     <<<BB, 1024>>>(mask_o);
    k_patches   <<<dim3(LL, BB), 128>>>();
    k_biT       <<<dim3(16, 9, BB), 256>>>();
    // GEMM1: S = bsn * fg^T  (mma.sync split-bf16) -> g_S
    k_mma       <<<dim3(8, 8, BB), 256, K_MMA_SMEM>>>(0);
    // fuse: g_S -> g_Sf -> g_S
    k_fuse_pass <<<dim3(LL / 256, LL, BB), 256>>>(0);
    k_fuse_pass <<<dim3(LL / 256, LL, BB), 256>>>(1);
    // softmax: reads fused g_S, writes score^T planes (g_A2h/l)
    k_softmax   <<<dim3(8, BB), 128>>>();
    // GEMM2: R[q][k'] = sum_p score[p][q] * bi[p][k'] -> g_R
    k_mma       <<<dim3(9, 8, BB), 256, K_MMA_SMEM>>>(1);
    k_out       <<<dim3(HH, BB), CC>>>(out);
}

// round 12
// speedup vs baseline: 2.0073x; 1.1969x over previous
#include <cuda_runtime.h>
#include <cuda_bf16.h>
#include <math.h>
#include <stdint.h>

// Problem constants
#define BB   16
#define CC   128
#define HH   64
#define WW   64
#define HR   32
#define WR   32
#define LL   1024          // HR*WR
#define KK   1152          // CC*9

// ---------------- scratch (device globals; only referenced from device code) --
__device__ float g_ft  [BB * HR * WR * CC];
__device__ float g_bt  [BB * HR * WR * CC];
__device__ float g_bot [BB * HH * WW * CC];
__device__ float g_bnorm[BB * LL];
__device__ float g_valid[BB * LL];
__device__ float g_S  [BB * LL * LL];                // raw S -> fused S
__device__ float g_Sf [BB * LL * LL];                // fuse stage 1
__device__ float g_R  [BB * LL * KK];
// bf16 split operands (row-major, k-minor)
__device__ __nv_bfloat16 g_A1h[BB * LL * KK];        // bsn hi   [b][p][k]
__device__ __nv_bfloat16 g_A1l[BB * LL * KK];        // bsn lo
__device__ __nv_bfloat16 g_B1h[BB * LL * KK];        // fg hi    [b][q][k]
__device__ __nv_bfloat16 g_B1l[BB * LL * KK];        // fg lo
__device__ __nv_bfloat16 g_A2h[BB * LL * LL];        // score^T hi [b][q][p]
__device__ __nv_bfloat16 g_A2l[BB * LL * LL];        // score^T lo
__device__ __nv_bfloat16 g_B2h[BB * KK * LL];        // bi^T hi  [b][k'][p]
__device__ __nv_bfloat16 g_B2l[BB * KK * LL];        // bi^T lo

// ---------------- PTX helpers (all baseline sm_80+, legal on compute_103) ----
__device__ __forceinline__ uint32_t smem_u32(const void* p) {
    uint32_t a;
    asm("{ .reg .u64 t; cvta.to.shared.u64 t, %1; cvt.u32.u64 %0, t; }" : "=r"(a) : "l"(p));
    return a;
}

#define CP_ASYNC16(dst, src) \
    asm volatile("cp.async.cg.shared.global [%0], [%1], 16;" :: "r"(dst), "l"(src))
#define CP_COMMIT() asm volatile("cp.async.commit_group;" ::: "memory")
#define CP_WAIT(n)  asm volatile("cp.async.wait_group %0;" :: "n"(n) : "memory")

#define LDSM_X4(r0, r1, r2, r3, addr) \
    asm volatile("ldmatrix.sync.aligned.m8n8.x4.shared.b16 {%0,%1,%2,%3}, [%4];" \
        : "=r"(r0), "=r"(r1), "=r"(r2), "=r"(r3) : "r"(addr))

#define MMA_BF16(c, a, b0, b1) \
    asm volatile("mma.sync.aligned.m16n8k16.row.col.f32.bf16.bf16.f32 " \
        "{%0,%1,%2,%3}, {%4,%5,%6,%7}, {%8,%9}, {%0,%1,%2,%3};" \
        : "+f"((c)[0]), "+f"((c)[1]), "+f"((c)[2]), "+f"((c)[3]) \
        : "r"((a)[0]), "r"((a)[1]), "r"((a)[2]), "r"((a)[3]), "r"(b0), "r"(b1))

// ---------------- transpose to channel-last ----------------------------------
__global__ void k_trans_ds(const float* __restrict__ src, int sel) {
    __shared__ float stage[HR * 129];
    const int y = blockIdx.x;
    const int b = blockIdx.y;
    float* dst = sel ? g_bt : g_ft;
    const int tid = threadIdx.x;
    for (int i = tid; i < HR * CC; i += 256) {
        int x = i & 31;
        int c = i >> 5;
        stage[x * 129 + c] = src[(((size_t)b * CC + c) * HH + 2 * y) * WW + 2 * x];
    }
    __syncthreads();
    for (int i = tid; i < HR * CC; i += 256) {
        int c = i & 127;
        int x = i >> 7;
        dst[(((size_t)b * HR + y) * WR + x) * CC + c] = stage[x * 129 + c];
    }
}

__global__ void k_trans_full(const float* __restrict__ src) {
    __shared__ float stage[WW * 129];
    const int y = blockIdx.x;
    const int b = blockIdx.y;
    const int tid = threadIdx.x;
    for (int i = tid; i < WW * CC; i += 256) {
        int x = i & 63;
        int c = i >> 6;
        stage[x * 129 + c] = src[(((size_t)b * CC + c) * HH + y) * WW + x];
    }
    __syncthreads();
    for (int i = tid; i < WW * CC; i += 256) {
        int c = i & 127;
        int x = i >> 7;
        g_bot[(((size_t)b * HH + y) * WW + x) * CC + c] = stage[x * 129 + c];
    }
}

// ---------------- bnorm -------------------------------------------------------
__global__ void k_bnorm() {
    __shared__ float ss[LL];
    const int b = blockIdx.x;
    const int tid = threadIdx.x;
    const int warp = tid >> 5, lane = tid & 31;
    for (int pos = warp; pos < LL; pos += 32) {
        float4 v = *(const float4*)&g_bt[((size_t)b * LL + pos) * CC + lane * 4];
        float s = v.x * v.x + v.y * v.y + v.z * v.z + v.w * v.w;
        #pragma unroll
        for (int o = 16; o; o >>= 1) s += __shfl_xor_sync(0xffffffffu, s, o);
        if (lane == 0) ss[pos] = s;
    }
    __syncthreads();
    const int p = tid, py = p >> 5, px = p & 31;
    float sum = 0.f;
    #pragma unroll
    for (int i = 0; i < 3; i++)
        #pragma unroll
        for (int j = 0; j < 3; j++) {
            int y = py + i - 1, x = px + j - 1;
            if ((unsigned)y < HR && (unsigned)x < WR) sum += ss[y * WR + x];
        }
    g_bnorm[b * LL + p] = fmaxf(sqrtf(sum), 1e-4f);
}

// ---------------- valid mask --------------------------------------------------
__global__ void k_valid(const float* __restrict__ mask_o) {
    __shared__ float md[LL];
    const int b = blockIdx.x;
    const int tid = threadIdx.x;
    md[tid] = mask_o[(size_t)b * HH * WW + (2 * (tid >> 5)) * WW + 2 * (tid & 31)];
    __syncthreads();
    const int py = tid >> 5, px = tid & 31;
    float sum = 0.f;
    #pragma unroll
    for (int i = 0; i < 3; i++)
        #pragma unroll
        for (int j = 0; j < 3; j++) {
            int y = py + i - 1, x = px + j - 1;
            if ((unsigned)y < HR && (unsigned)x < WR) sum += md[y * WR + x];
        }
    g_valid[b * LL + tid] = (sum == 0.f) ? 1.f : 0.f;
}

// ---------------- patch matrices -> bf16 hi/lo planes -------------------------
__global__ void k_patches() {
    const int p = blockIdx.x;
    const int b = blockIdx.y;
    const int c = threadIdx.x;
    const int py = p >> 5, px = p & 31;
    const float nrm = g_bnorm[b * LL + p];
    const size_t rowb = ((size_t)b * LL + p) * KK;
    #pragma unroll
    for (int ij = 0; ij < 9; ij++) {
        const int i = ij / 3, j = ij % 3;
        const int y = py + i - 1, x = px + j - 1;
        float fv = 0.f, bv = 0.f;
        if ((unsigned)y < HR && (unsigned)x < WR) {
            size_t o = (((size_t)b * HR + y) * WR + x) * CC + c;
            fv = g_ft[o];
            bv = g_bt[o];
        }
        const float sv = bv / nrm;
        const size_t idx = rowb + ij * CC + c;
        __nv_bfloat16 h = __float2bfloat16(sv);
        g_A1h[idx] = h;
        g_A1l[idx] = __float2bfloat16(sv - __bfloat162float(h));
        h = __float2bfloat16(fv);
        g_B1h[idx] = h;
        g_B1l[idx] = __float2bfloat16(fv - __bfloat162float(h));
    }
}

// ---------------- bi^T planes (GEMM2 B): rows k' = ij*128+c, cols p -----------
__global__ void k_biT() {
    __shared__ float stage[64 * 129];
    const int pc = blockIdx.x;     // p chunk (0..15), 64 wide
    const int t  = blockIdx.y;     // ij (0..8)
    const int b  = blockIdx.z;
    const int i = t / 3, j = t % 3;
    const int tid = threadIdx.x;   // 256
    for (int idx = tid; idx < 8192; idx += 256) {
        int pl = idx >> 7, rr = idx & 127;   // pl: local p, rr: channel
        int p = pc * 64 + pl;
        int y = 2 * (p >> 5) + i - 1, x = 2 * (p & 31) + j - 1;
        float v = 0.f;
        if ((unsigned)y < HH && (unsigned)x < WW)
            v = g_bot[(((size_t)b * HH + y) * WW + x) * CC + rr];
        stage[pl * 129 + rr] = v;
    }
    __syncthreads();
    for (int idx = tid; idx < 8192; idx += 256) {
        int rr = idx >> 6, cc = idx & 63;    // rr: channel, cc: local p
        float v = stage[cc * 129 + rr];
        const size_t o = (((size_t)b * KK + t * 128 + rr) << 10) + pc * 64 + cc;
        __nv_bfloat16 h = __float2bfloat16(v);
        g_B2h[o] = h;
        g_B2l[o] = __float2bfloat16(v - __bfloat162float(h));
    }
}

// ---------------- mma.sync split-bf16 GEMM ------------------------------------
// sel 0: S[p][q]  = sum_k bsn[p][k]*fg[q][k]          (M=N=1024, K=1152)
// sel 1: R[q][k'] = sum_p scoreT[q][p]*biT[k'][p]     (M=1024, N=1152, K=1024)
// CTA tile 128x128, BK=32, 8 warps @ 32x64, double-buffered cp.async.
#define SM_STRIDE 40                 // padded bf16 elems per smem row
#define TILE_BYTES (128 * SM_STRIDE * 2)   // 10240
#define STAGE_BYTES (4 * TILE_BYTES)       // Ah, Al, Bh, Bl
#define K_MMA_SMEM (2 * STAGE_BYTES)       // 81920

__global__ void __launch_bounds__(256) k_mma(int sel) {
    extern __shared__ __align__(16) char smem[];
    const uint32_t sbase = smem_u32(smem);
    const int tid = threadIdx.x;
    const int lane = tid & 31, wid = tid >> 5;
    const int wm = (wid & 3) * 32;       // warp m offset in tile
    const int wn = (wid >> 2) * 64;      // warp n offset in tile
    const int b = blockIdx.z, my = blockIdx.y, nx = blockIdx.x;

    const int Kdim = sel ? LL : KK;
    const int Ncols = sel ? KK : LL;     // C row stride
    const __nv_bfloat16* Ah = sel ? g_A2h + ((size_t)b << 20) : g_A1h + (size_t)b * LL * KK;
    const __nv_bfloat16* Al = sel ? g_A2l + ((size_t)b << 20) : g_A1l + (size_t)b * LL * KK;
    const __nv_bfloat16* Bh = sel ? g_B2h + (size_t)b * KK * LL : g_B1h + (size_t)b * LL * KK;
    const __nv_bfloat16* Bl = sel ? g_B2l + (size_t)b * KK * LL : g_B1l + (size_t)b * LL * KK;
    float* Cb = sel ? g_R + (size_t)b * LL * KK : g_S + ((size_t)b << 20);

    const int iters = Kdim / 32;

    float acc[2][8][4];
    #pragma unroll
    for (int mt = 0; mt < 2; mt++)
        #pragma unroll
        for (int nt = 0; nt < 8; nt++)
            #pragma unroll
            for (int u = 0; u < 4; u++) acc[mt][nt][u] = 0.f;

    // ---- stage loader ----
    auto load_stage = [&](int kt, int buf) {
        const uint32_t sdst = sbase + buf * STAGE_BYTES;
        #pragma unroll
        for (int t = 0; t < 4; t++) {
            const __nv_bfloat16* src = (t == 0) ? Ah : (t == 1) ? Al : (t == 2) ? Bh : Bl;
            const int rowbase = (t < 2) ? my * 128 : nx * 128;
            #pragma unroll
            for (int u = 0; u < 2; u++) {
                const int id = tid * 2 + u;             // 0..511
                const int r = id >> 2, c4 = id & 3;     // row, 16B-chunk (8 elems)
                const uint32_t d = sdst + t * TILE_BYTES + (r * SM_STRIDE + c4 * 8) * 2;
                const __nv_bfloat16* s = src + (size_t)(rowbase + r) * Kdim + kt + c4 * 8;
                CP_ASYNC16(d, s);
            }
        }
        CP_COMMIT();
    };

    load_stage(0, 0);

    for (int i = 0; i < iters; i++) {
        const int buf = i & 1;
        if (i + 1 < iters) load_stage((i + 1) * 32, buf ^ 1);
        if (i + 1 < iters) { CP_WAIT(1); } else { CP_WAIT(0); }
        __syncthreads();

        const uint32_t sa = sbase + buf * STAGE_BYTES;
        const uint32_t pAh = sa, pAl = sa + TILE_BYTES;
        const uint32_t pBh = sa + 2 * TILE_BYTES, pBl = sa + 3 * TILE_BYTES;

        #pragma unroll
        for (int ks = 0; ks < 2; ks++) {
            uint32_t ah[2][4], al[2][4];
            #pragma unroll
            for (int mt = 0; mt < 2; mt++) {
                const int r = wm + mt * 16 + (lane & 15);
                const uint32_t off = (uint32_t)(r * SM_STRIDE + ks * 16 + ((lane >> 4) << 3)) * 2;
                LDSM_X4(ah[mt][0], ah[mt][1], ah[mt][2], ah[mt][3], pAh + off);
                LDSM_X4(al[mt][0], al[mt][1], al[mt][2], al[mt][3], pAl + off);
            }
            #pragma unroll
            for (int np = 0; np < 4; np++) {
                const int rn = wn + np * 16 + (lane & 7) + ((lane >> 4) << 3);
                const uint32_t off = (uint32_t)(rn * SM_STRIDE + ks * 16 + (((lane >> 3) & 1) << 3)) * 2;
                uint32_t bh4[4], bl4[4];
                LDSM_X4(bh4[0], bh4[1], bh4[2], bh4[3], pBh + off);
                LDSM_X4(bl4[0], bl4[1], bl4[2], bl4[3], pBl + off);
                #pragma unroll
                for (int h2 = 0; h2 < 2; h2++) {
                    const int nt = np * 2 + h2;
                    #pragma unroll
                    for (int mt = 0; mt < 2; mt++) {
                        MMA_BF16(acc[mt][nt], ah[mt], bh4[h2 * 2], bh4[h2 * 2 + 1]);
                        MMA_BF16(acc[mt][nt], ah[mt], bl4[h2 * 2], bl4[h2 * 2 + 1]);
                        MMA_BF16(acc[mt][nt], al[mt], bh4[h2 * 2], bh4[h2 * 2 + 1]);
                    }
                }
            }
        }
        __syncthreads();
    }

    // ---- store C ----
    #pragma unroll
    for (int mt = 0; mt < 2; mt++) {
        const int row0 = my * 128 + wm + mt * 16 + (lane >> 2);
        #pragma unroll
        for (int nt = 0; nt < 8; nt++) {
            const int col = nx * 128 + wn + nt * 8 + (lane & 3) * 2;
            float* c0 = Cb + (size_t)row0 * Ncols + col;
            float* c1 = Cb + (size_t)(row0 + 8) * Ncols + col;
            c0[0] = acc[mt][nt][0]; c0[1] = acc[mt][nt][1];
            c1[0] = acc[mt][nt][2]; c1[1] = acc[mt][nt][3];
        }
    }
}

// ---------------- fuse: coalesced diag-fuse passes ----------------------------
// Mapping (identical to previous rounds, re-indexed for coalescing):
//   dst[tsw(p)][tsw(q)] = sum_{d=-1..1} src[p+d][q+d]
// Reads: 3 contiguous rows. Writes: contiguous row, permuted via padded SMEM.
__global__ void k_fuse_pass(int stage) {
    __shared__ float vbuf[LL + 32];       // padded: idx = q + (q>>5)
    const int ph = blockIdx.x;            // 0..31
    const int b  = blockIdx.y;
    const float* src = (stage ? g_Sf : g_S) + ((size_t)b << 20);
    float*       dst = (stage ? g_S  : g_Sf) + ((size_t)b << 20);
    const int tid = threadIdx.x;          // 256
    for (int pl = 0; pl < 32; pl++) {
        const int p = ph * 32 + pl;
        #pragma unroll
        for (int k = 0; k < 4; k++) {
            const int q = tid + k * 256;
            float acc = 0.f;
            #pragma unroll
            for (int d = -1; d <= 1; d++) {
                const int pp = p + d, qq = q + d;
                if ((unsigned)pp < LL && (unsigned)qq < LL)
                    acc += src[((size_t)pp << 10) + qq];
            }
            vbuf[q + (q >> 5)] = acc;
        }
        __syncthreads();
        const int rp = pl * 32 + ph;      // tsw(p)
        #pragma unroll
        for (int k = 0; k < 4; k++) {
            const int cp = tid + k * 256;
            const int q = ((cp & 31) << 5) | (cp >> 5);   // tsw(cp)
            dst[((size_t)rp << 10) + cp] = vbuf[q + (q >> 5)];
        }
        __syncthreads();
    }
}

// ---------------- softmax over p; writes score^T hi/lo rows -------------------
__global__ void k_softmax() {
    __shared__ float sval[LL];
    __shared__ float stage[128 * 65];
    const int qt = blockIdx.x;     // 0..7
    const int b  = blockIdx.y;
    const int ql = threadIdx.x;    // 128 threads
    const int q = qt * 128 + ql;
    for (int i = ql; i < LL; i += 128) sval[i] = g_valid[b * LL + i];
    __syncthreads();
    const float* S = g_S + ((size_t)b << 20);
    float mx = -1e30f;
    for (int p = 0; p < LL; p++)
        mx = fmaxf(mx, S[((size_t)p << 10) + q] * sval[p] * 10.f);
    float sum = 0.f;
    for (int p = 0; p < LL; p++)
        sum += expf(S[((size_t)p << 10) + q] * sval[p] * 10.f - mx);
    const float inv = 1.f / sum;
    for (int pc = 0; pc < 16; pc++) {
        for (int pl = 0; pl < 64; pl++) {
            const int p = pc * 64 + pl;
            stage[ql * 65 + pl] = expf(S[((size_t)p << 10) + q] * sval[p] * 10.f - mx) * inv * sval[p];
        }
        __syncthreads();
        // write scoreT rows: row = qt*128 + rr, cols pc*64 + cc
        for (int idx = ql; idx < 8192; idx += 128) {
            const int rr = idx >> 6, cc = idx & 63;
            const float v = stage[rr * 65 + cc];
            const size_t o = ((((size_t)b << 10) + qt * 128 + rr) << 10) + pc * 64 + cc;
            __nv_bfloat16 h = __float2bfloat16(v);
            g_A2h[o] = h;
            g_A2l[o] = __float2bfloat16(v - __bfloat162float(h));
        }
        __syncthreads();
    }
}

// ---------------- transposed-conv gather from R -------------------------------
__global__ void k_out(float* __restrict__ out) {
    const int y = blockIdx.x;
    const int b = blockIdx.y;
    const int c = threadIdx.x;
    int qylo = (y - 1) < 0 ? 0 : (y - 1) >> 1;
    int qyhi = (y + 1) >> 1; if (qyhi > 31) qyhi = 31;
    for (int x = 0; x < WW; x++) {
        int qxlo = (x - 1) < 0 ? 0 : (x - 1) >> 1;
        int qxhi = (x + 1) >> 1; if (qxhi > 31) qxhi = 31;
        float acc = 0.f;
        for (int qy = qylo; qy <= qyhi; qy++) {
            const int i = y - 2 * qy + 1;
            if (i < 0 || i > 2) continue;
            for (int qx = qxlo; qx <= qxhi; qx++) {
                const int j = x - 2 * qx + 1;
                if (j < 0 || j > 2) continue;
                const int q = qy * WR + qx;
                acc += g_R[(((size_t)b * LL + q) * 9 + i * 3 + j) * CC + c];
            }
        }
        out[(((size_t)b * CC + c) * HH + y) * WW + x] = acc * 0.25f;
    }
}

// ---------------- orchestration ----------------------------------------------
extern "C" void kernel_launch(void* const* d_in, const int* in_sizes, int n_in,
                              void* d_out, int out_size) {
    const float* big[2] = {nullptr, nullptr};
    const float* mask_o = nullptr;
    int nb = 0;
    for (int i = 0; i < n_in && i < 3; i++) {
        if (in_sizes[i] == BB * 1 * HH * WW) {
            mask_o = (const float*)d_in[i];
        } else if (nb < 2) {
            big[nb++] = (const float*)d_in[i];
        }
    }
    const float* f_o = big[0] ? big[0] : (const float*)d_in[0];
    const float* b_o = big[1] ? big[1] : (const float*)d_in[1];
    if (!mask_o) mask_o = (const float*)d_in[2];
    float* out = (float*)d_out;

    cudaFuncSetAttribute(k_mma, cudaFuncAttributeMaxDynamicSharedMemorySize, K_MMA_SMEM);

    k_trans_ds  <<<dim3(HR, BB), 256>>>(f_o, 0);
    k_trans_ds  <<<dim3(HR, BB), 256>>>(b_o, 1);
    k_trans_full<<<dim3(HH, BB), 256>>>(b_o);
    k_bnorm     <<<BB, 1024>>>();
    k_valid     <<<BB, 1024>>>(mask_o);
    k_patches   <<<dim3(LL, BB), 128>>>();
    k_biT       <<<dim3(16, 9, BB), 256>>>();
    // GEMM1: S = bsn * fg^T  (mma.sync split-bf16) -> g_S
    k_mma       <<<dim3(8, 8, BB), 256, K_MMA_SMEM>>>(0);
    // fuse: g_S -> g_Sf -> g_S (coalesced passes)
    k_fuse_pass <<<dim3(32, BB), 256>>>(0);
    k_fuse_pass <<<dim3(32, BB), 256>>>(1);
    // softmax: reads fused g_S, writes score^T planes (g_A2h/l)
    k_softmax   <<<dim3(8, BB), 128>>>();
    // GEMM2: R[q][k'] = sum_p score[p][q] * bi[p][k'] -> g_R
    k_mma       <<<dim3(9, 8, BB), 256, K_MMA_SMEM>>>(1);
    k_out       <<<dim3(HH, BB), CC>>>(out);
}

// round 13
// speedup vs baseline: 2.5236x; 1.2572x over previous
#include <cuda_runtime.h>
#include <cuda_bf16.h>
#include <math.h>
#include <stdint.h>

// Problem constants
#define BB   16
#define CC   128
#define HH   64
#define WW   64
#define HR   32
#define WR   32
#define LL   1024          // HR*WR
#define KK   1152          // CC*9

// ---------------- scratch (device globals; only referenced from device code) --
__device__ float g_ft  [BB * HR * WR * CC];
__device__ float g_bt  [BB * HR * WR * CC];
__device__ float g_bot [BB * HH * WW * CC];
__device__ float g_bnorm[BB * LL];
__device__ float g_valid[BB * LL];
__device__ float g_S  [BB * LL * LL];                // assembled S -> fused S
__device__ float g_Sf [BB * LL * LL];                // raw G / fuse stage 1
__device__ float g_R  [BB * LL * KK];
// bf16 split operand planes
__device__ __nv_bfloat16 g_A1h[BB * LL * CC];        // bt hi   [b][u][c]
__device__ __nv_bfloat16 g_A1l[BB * LL * CC];        // bt lo
__device__ __nv_bfloat16 g_B1h[BB * LL * CC];        // ft hi   [b][v][c]
__device__ __nv_bfloat16 g_B1l[BB * LL * CC];        // ft lo
__device__ __nv_bfloat16 g_A2h[BB * LL * LL];        // score^T hi [b][q][p]
__device__ __nv_bfloat16 g_A2l[BB * LL * LL];        // score^T lo
__device__ __nv_bfloat16 g_B2h[BB * KK * LL];        // bi^T hi  [b][k'][p]
__device__ __nv_bfloat16 g_B2l[BB * KK * LL];        // bi^T lo

// ---------------- PTX helpers (all baseline sm_80+, legal on compute_103) ----
__device__ __forceinline__ uint32_t smem_u32(const void* p) {
    uint32_t a;
    asm("{ .reg .u64 t; cvta.to.shared.u64 t, %1; cvt.u32.u64 %0, t; }" : "=r"(a) : "l"(p));
    return a;
}

#define CP_ASYNC16(dst, src) \
    asm volatile("cp.async.cg.shared.global [%0], [%1], 16;" :: "r"(dst), "l"(src))
#define CP_COMMIT() asm volatile("cp.async.commit_group;" ::: "memory")
#define CP_WAIT(n)  asm volatile("cp.async.wait_group %0;" :: "n"(n) : "memory")

#define LDSM_X4(r0, r1, r2, r3, addr) \
    asm volatile("ldmatrix.sync.aligned.m8n8.x4.shared.b16 {%0,%1,%2,%3}, [%4];" \
        : "=r"(r0), "=r"(r1), "=r"(r2), "=r"(r3) : "r"(addr))

#define MMA_BF16(c, a, b0, b1) \
    asm volatile("mma.sync.aligned.m16n8k16.row.col.f32.bf16.bf16.f32 " \
        "{%0,%1,%2,%3}, {%4,%5,%6,%7}, {%8,%9}, {%0,%1,%2,%3};" \
        : "+f"((c)[0]), "+f"((c)[1]), "+f"((c)[2]), "+f"((c)[3]) \
        : "r"((a)[0]), "r"((a)[1]), "r"((a)[2]), "r"((a)[3]), "r"(b0), "r"(b1))

// ---------------- transpose to channel-last ----------------------------------
__global__ void k_trans_ds(const float* __restrict__ src, int sel) {
    __shared__ float stage[HR * 129];
    const int y = blockIdx.x;
    const int b = blockIdx.y;
    float* dst = sel ? g_bt : g_ft;
    const int tid = threadIdx.x;
    for (int i = tid; i < HR * CC; i += 256) {
        int x = i & 31;
        int c = i >> 5;
        stage[x * 129 + c] = src[(((size_t)b * CC + c) * HH + 2 * y) * WW + 2 * x];
    }
    __syncthreads();
    for (int i = tid; i < HR * CC; i += 256) {
        int c = i & 127;
        int x = i >> 7;
        dst[(((size_t)b * HR + y) * WR + x) * CC + c] = stage[x * 129 + c];
    }
}

__global__ void k_trans_full(const float* __restrict__ src) {
    __shared__ float stage[WW * 129];
    const int y = blockIdx.x;
    const int b = blockIdx.y;
    const int tid = threadIdx.x;
    for (int i = tid; i < WW * CC; i += 256) {
        int x = i & 63;
        int c = i >> 6;
        stage[x * 129 + c] = src[(((size_t)b * CC + c) * HH + y) * WW + x];
    }
    __syncthreads();
    for (int i = tid; i < WW * CC; i += 256) {
        int c = i & 127;
        int x = i >> 7;
        g_bot[(((size_t)b * HH + y) * WW + x) * CC + c] = stage[x * 129 + c];
    }
}

// ---------------- bnorm -------------------------------------------------------
__global__ void k_bnorm() {
    __shared__ float ss[LL];
    const int b = blockIdx.x;
    const int tid = threadIdx.x;
    const int warp = tid >> 5, lane = tid & 31;
    for (int pos = warp; pos < LL; pos += 32) {
        float4 v = *(const float4*)&g_bt[((size_t)b * LL + pos) * CC + lane * 4];
        float s = v.x * v.x + v.y * v.y + v.z * v.z + v.w * v.w;
        #pragma unroll
        for (int o = 16; o; o >>= 1) s += __shfl_xor_sync(0xffffffffu, s, o);
        if (lane == 0) ss[pos] = s;
    }
    __syncthreads();
    const int p = tid, py = p >> 5, px = p & 31;
    float sum = 0.f;
    #pragma unroll
    for (int i = 0; i < 3; i++)
        #pragma unroll
        for (int j = 0; j < 3; j++) {
            int y = py + i - 1, x = px + j - 1;
            if ((unsigned)y < HR && (unsigned)x < WR) sum += ss[y * WR + x];
        }
    g_bnorm[b * LL + p] = fmaxf(sqrtf(sum), 1e-4f);
}

// ---------------- valid mask --------------------------------------------------
__global__ void k_valid(const float* __restrict__ mask_o) {
    __shared__ float md[LL];
    const int b = blockIdx.x;
    const int tid = threadIdx.x;
    md[tid] = mask_o[(size_t)b * HH * WW + (2 * (tid >> 5)) * WW + 2 * (tid & 31)];
    __syncthreads();
    const int py = tid >> 5, px = tid & 31;
    float sum = 0.f;
    #pragma unroll
    for (int i = 0; i < 3; i++)
        #pragma unroll
        for (int j = 0; j < 3; j++) {
            int y = py + i - 1, x = px + j - 1;
            if ((unsigned)y < HR && (unsigned)x < WR) sum += md[y * WR + x];
        }
    g_valid[b * LL + tid] = (sum == 0.f) ? 1.f : 0.f;
}

// ---------------- bf16 hi/lo planes of ft/bt (replaces fg/bsn production) -----
__global__ void k_conv_planes() {
    const size_t i = (size_t)blockIdx.x * 256 + threadIdx.x;   // over BB*LL*CC
    const float bv = g_bt[i], fv = g_ft[i];
    __nv_bfloat16 h = __float2bfloat16(bv);
    g_A1h[i] = h;
    g_A1l[i] = __float2bfloat16(bv - __bfloat162float(h));
    h = __float2bfloat16(fv);
    g_B1h[i] = h;
    g_B1l[i] = __float2bfloat16(fv - __bfloat162float(h));
}

// ---------------- bi^T planes (GEMM2 B): rows k' = ij*128+c, cols p -----------
__global__ void k_biT() {
    __shared__ float stage[64 * 129];
    const int pc = blockIdx.x;     // p chunk (0..15), 64 wide
    const int t  = blockIdx.y;     // ij (0..8)
    const int b  = blockIdx.z;
    const int i = t / 3, j = t % 3;
    const int tid = threadIdx.x;   // 256
    for (int idx = tid; idx < 8192; idx += 256) {
        int pl = idx >> 7, rr = idx & 127;   // pl: local p, rr: channel
        int p = pc * 64 + pl;
        int y = 2 * (p >> 5) + i - 1, x = 2 * (p & 31) + j - 1;
        float v = 0.f;
        if ((unsigned)y < HH && (unsigned)x < WW)
            v = g_bot[(((size_t)b * HH + y) * WW + x) * CC + rr];
        stage[pl * 129 + rr] = v;
    }
    __syncthreads();
    for (int idx = tid; idx < 8192; idx += 256) {
        int rr = idx >> 6, cc = idx & 63;    // rr: channel, cc: local p
        float v = stage[cc * 129 + rr];
        const size_t o = (((size_t)b * KK + t * 128 + rr) << 10) + pc * 64 + cc;
        __nv_bfloat16 h = __float2bfloat16(v);
        g_B2h[o] = h;
        g_B2l[o] = __float2bfloat16(v - __bfloat162float(h));
    }
}

// ---------------- mma.sync split-bf16 GEMM ------------------------------------
// sel 0: G[u][v]  = sum_c bt[u][c]*ft[v][c]           (M=N=1024, K=128)  -> g_Sf
// sel 1: R[q][k'] = sum_p scoreT[q][p]*biT[k'][p]     (M=1024, N=1152, K=1024)
// CTA tile 128x128, BK=32, 8 warps @ 32x64, double-buffered cp.async.
#define SM_STRIDE 40                 // padded bf16 elems per smem row
#define TILE_BYTES (128 * SM_STRIDE * 2)   // 10240
#define STAGE_BYTES (4 * TILE_BYTES)       // Ah, Al, Bh, Bl
#define K_MMA_SMEM (2 * STAGE_BYTES)       // 81920

__global__ void __launch_bounds__(256) k_mma(int sel) {
    extern __shared__ __align__(16) char smem[];
    const uint32_t sbase = smem_u32(smem);
    const int tid = threadIdx.x;
    const int lane = tid & 31, wid = tid >> 5;
    const int wm = (wid & 3) * 32;       // warp m offset in tile
    const int wn = (wid >> 2) * 64;      // warp n offset in tile
    const int b = blockIdx.z, my = blockIdx.y, nx = blockIdx.x;

    const int Kdim = sel ? LL : CC;
    const int Ncols = sel ? KK : LL;     // C row stride
    const __nv_bfloat16* Ah = sel ? g_A2h + ((size_t)b << 20) : g_A1h + (size_t)b * LL * CC;
    const __nv_bfloat16* Al = sel ? g_A2l + ((size_t)b << 20) : g_A1l + (size_t)b * LL * CC;
    const __nv_bfloat16* Bh = sel ? g_B2h + (size_t)b * KK * LL : g_B1h + (size_t)b * LL * CC;
    const __nv_bfloat16* Bl = sel ? g_B2l + (size_t)b * KK * LL : g_B1l + (size_t)b * LL * CC;
    float* Cb = sel ? g_R + (size_t)b * LL * KK : g_Sf + ((size_t)b << 20);

    const int iters = Kdim / 32;

    float acc[2][8][4];
    #pragma unroll
    for (int mt = 0; mt < 2; mt++)
        #pragma unroll
        for (int nt = 0; nt < 8; nt++)
            #pragma unroll
            for (int u = 0; u < 4; u++) acc[mt][nt][u] = 0.f;

    // ---- stage loader ----
    auto load_stage = [&](int kt, int buf) {
        const uint32_t sdst = sbase + buf * STAGE_BYTES;
        #pragma unroll
        for (int t = 0; t < 4; t++) {
            const __nv_bfloat16* src = (t == 0) ? Ah : (t == 1) ? Al : (t == 2) ? Bh : Bl;
            const int rowbase = (t < 2) ? my * 128 : nx * 128;
            #pragma unroll
            for (int u = 0; u < 2; u++) {
                const int id = tid * 2 + u;             // 0..511
                const int r = id >> 2, c4 = id & 3;     // row, 16B-chunk (8 elems)
                const uint32_t d = sdst + t * TILE_BYTES + (r * SM_STRIDE + c4 * 8) * 2;
                const __nv_bfloat16* s = src + (size_t)(rowbase + r) * Kdim + kt + c4 * 8;
                CP_ASYNC16(d, s);
            }
        }
        CP_COMMIT();
    };

    load_stage(0, 0);

    for (int i = 0; i < iters; i++) {
        const int buf = i & 1;
        if (i + 1 < iters) load_stage((i + 1) * 32, buf ^ 1);
        if (i + 1 < iters) { CP_WAIT(1); } else { CP_WAIT(0); }
        __syncthreads();

        const uint32_t sa = sbase + buf * STAGE_BYTES;
        const uint32_t pAh = sa, pAl = sa + TILE_BYTES;
        const uint32_t pBh = sa + 2 * TILE_BYTES, pBl = sa + 3 * TILE_BYTES;

        #pragma unroll
        for (int ks = 0; ks < 2; ks++) {
            uint32_t ah[2][4], al[2][4];
            #pragma unroll
            for (int mt = 0; mt < 2; mt++) {
                const int r = wm + mt * 16 + (lane & 15);
                const uint32_t off = (uint32_t)(r * SM_STRIDE + ks * 16 + ((lane >> 4) << 3)) * 2;
                LDSM_X4(ah[mt][0], ah[mt][1], ah[mt][2], ah[mt][3], pAh + off);
                LDSM_X4(al[mt][0], al[mt][1], al[mt][2], al[mt][3], pAl + off);
            }
            #pragma unroll
            for (int np = 0; np < 4; np++) {
                const int rn = wn + np * 16 + (lane & 7) + ((lane >> 4) << 3);
                const uint32_t off = (uint32_t)(rn * SM_STRIDE + ks * 16 + (((lane >> 3) & 1) << 3)) * 2;
                uint32_t bh4[4], bl4[4];
                LDSM_X4(bh4[0], bh4[1], bh4[2], bh4[3], pBh + off);
                LDSM_X4(bl4[0], bl4[1], bl4[2], bl4[3], pBl + off);
                #pragma unroll
                for (int h2 = 0; h2 < 2; h2++) {
                    const int nt = np * 2 + h2;
                    #pragma unroll
                    for (int mt = 0; mt < 2; mt++) {
                        MMA_BF16(acc[mt][nt], ah[mt], bh4[h2 * 2], bh4[h2 * 2 + 1]);
                        MMA_BF16(acc[mt][nt], ah[mt], bl4[h2 * 2], bl4[h2 * 2 + 1]);
                        MMA_BF16(acc[mt][nt], al[mt], bh4[h2 * 2], bh4[h2 * 2 + 1]);
                    }
                }
            }
        }
        __syncthreads();
    }

    // ---- store C ----
    #pragma unroll
    for (int mt = 0; mt < 2; mt++) {
        const int row0 = my * 128 + wm + mt * 16 + (lane >> 2);
        #pragma unroll
        for (int nt = 0; nt < 8; nt++) {
            const int col = nx * 128 + wn + nt * 8 + (lane & 3) * 2;
            float* c0 = Cb + (size_t)row0 * Ncols + col;
            float* c1 = Cb + (size_t)(row0 + 8) * Ncols + col;
            c0[0] = acc[mt][nt][0]; c0[1] = acc[mt][nt][1];
            c1[0] = acc[mt][nt][2]; c1[1] = acc[mt][nt][3];
        }
    }
}

// ---------------- S assembly: 9-tap 2D shift-sum of G, scaled by 1/nrm --------
// S[p,q] = (1/nrm_p) * sum_{di,dj in {-1,0,1}} G[p2d+(di,dj), q2d+(di,dj)]
__global__ void k_sassy() {
    const int b = blockIdx.z;
    const int p = blockIdx.y;
    const int q = blockIdx.x * 256 + threadIdx.x;
    const int py = p >> 5, px = p & 31;
    const int qy = q >> 5, qx = q & 31;
    const float inv = 1.f / g_bnorm[b * LL + p];
    const float* G = g_Sf + ((size_t)b << 20);
    float acc = 0.f;
    #pragma unroll
    for (int di = -1; di <= 1; di++) {
        if ((unsigned)(py + di) >= HR || (unsigned)(qy + di) >= HR) continue;
        #pragma unroll
        for (int dj = -1; dj <= 1; dj++) {
            if ((unsigned)(px + dj) >= WR || (unsigned)(qx + dj) >= WR) continue;
            const int s = di * 32 + dj;
            acc += G[((size_t)(p + s) << 10) + (q + s)];
        }
    }
    g_S[((size_t)b << 20) + ((size_t)p << 10) + q] = acc * inv;
}

// ---------------- fuse: coalesced diag-fuse passes ----------------------------
// dst[tsw(p)][tsw(q)] = sum_{d=-1..1} src[p+d][q+d]
__global__ void k_fuse_pass(int stage) {
    __shared__ float vbuf[LL + 32];       // padded: idx = q + (q>>5)
    const int ph = blockIdx.x;            // 0..31
    const int b  = blockIdx.y;
    const float* src = (stage ? g_Sf : g_S) + ((size_t)b << 20);
    float*       dst = (stage ? g_S  : g_Sf) + ((size_t)b << 20);
    const int tid = threadIdx.x;          // 256
    for (int pl = 0; pl < 32; pl++) {
        const int p = ph * 32 + pl;
        #pragma unroll
        for (int k = 0; k < 4; k++) {
            const int q = tid + k * 256;
            float acc = 0.f;
            #pragma unroll
            for (int d = -1; d <= 1; d++) {
                const int pp = p + d, qq = q + d;
                if ((unsigned)pp < LL && (unsigned)qq < LL)
                    acc += src[((size_t)pp << 10) + qq];
            }
            vbuf[q + (q >> 5)] = acc;
        }
        __syncthreads();
        const int rp = pl * 32 + ph;      // tsw(p)
        #pragma unroll
        for (int k = 0; k < 4; k++) {
            const int cp = tid + k * 256;
            const int q = ((cp & 31) << 5) | (cp >> 5);   // tsw(cp)
            dst[((size_t)rp << 10) + cp] = vbuf[q + (q >> 5)];
        }
        __syncthreads();
    }
}

// ---------------- softmax over p; writes score^T hi/lo rows -------------------
__global__ void k_softmax() {
    __shared__ float sval[LL];
    __shared__ float stage[128 * 65];
    const int qt = blockIdx.x;     // 0..7
    const int b  = blockIdx.y;
    const int ql = threadIdx.x;    // 128 threads
    const int q = qt * 128 + ql;
    for (int i = ql; i < LL; i += 128) sval[i] = g_valid[b * LL + i];
    __syncthreads();
    const float* S = g_S + ((size_t)b << 20);
    float mx = -1e30f;
    for (int p = 0; p < LL; p++)
        mx = fmaxf(mx, S[((size_t)p << 10) + q] * sval[p] * 10.f);
    float sum = 0.f;
    for (int p = 0; p < LL; p++)
        sum += expf(S[((size_t)p << 10) + q] * sval[p] * 10.f - mx);
    const float inv = 1.f / sum;
    for (int pc = 0; pc < 16; pc++) {
        for (int pl = 0; pl < 64; pl++) {
            const int p = pc * 64 + pl;
            stage[ql * 65 + pl] = expf(S[((size_t)p << 10) + q] * sval[p] * 10.f - mx) * inv * sval[p];
        }
        __syncthreads();
        // write scoreT rows: row = qt*128 + rr, cols pc*64 + cc
        for (int idx = ql; idx < 8192; idx += 128) {
            const int rr = idx >> 6, cc = idx & 63;
            const float v = stage[rr * 65 + cc];
            const size_t o = ((((size_t)b << 10) + qt * 128 + rr) << 10) + pc * 64 + cc;
            __nv_bfloat16 h = __float2bfloat16(v);
            g_A2h[o] = h;
            g_A2l[o] = __float2bfloat16(v - __bfloat162float(h));
        }
        __syncthreads();
    }
}

// ---------------- transposed-conv gather from R -------------------------------
__global__ void k_out(float* __restrict__ out) {
    const int y = blockIdx.x;
    const int b = blockIdx.y;
    const int c = threadIdx.x;
    int qylo = (y - 1) < 0 ? 0 : (y - 1) >> 1;
    int qyhi = (y + 1) >> 1; if (qyhi > 31) qyhi = 31;
    for (int x = 0; x < WW; x++) {
        int qxlo = (x - 1) < 0 ? 0 : (x - 1) >> 1;
        int qxhi = (x + 1) >> 1; if (qxhi > 31) qxhi = 31;
        float acc = 0.f;
        for (int qy = qylo; qy <= qyhi; qy++) {
            const int i = y - 2 * qy + 1;
            if (i < 0 || i > 2) continue;
            for (int qx = qxlo; qx <= qxhi; qx++) {
                const int j = x - 2 * qx + 1;
                if (j < 0 || j > 2) continue;
                const int q = qy * WR + qx;
                acc += g_R[(((size_t)b * LL + q) * 9 + i * 3 + j) * CC + c];
            }
        }
        out[(((size_t)b * CC + c) * HH + y) * WW + x] = acc * 0.25f;
    }
}

// ---------------- orchestration ----------------------------------------------
extern "C" void kernel_launch(void* const* d_in, const int* in_sizes, int n_in,
                              void* d_out, int out_size) {
    const float* big[2] = {nullptr, nullptr};
    const float* mask_o = nullptr;
    int nb = 0;
    for (int i = 0; i < n_in && i < 3; i++) {
        if (in_sizes[i] == BB * 1 * HH * WW) {
            mask_o = (const float*)d_in[i];
        } else if (nb < 2) {
            big[nb++] = (const float*)d_in[i];
        }
    }
    const float* f_o = big[0] ? big[0] : (const float*)d_in[0];
    const float* b_o = big[1] ? big[1] : (const float*)d_in[1];
    if (!mask_o) mask_o = (const float*)d_in[2];
    float* out = (float*)d_out;

    cudaFuncSetAttribute(k_mma, cudaFuncAttributeMaxDynamicSharedMemorySize, K_MMA_SMEM);

    k_trans_ds  <<<dim3(HR, BB), 256>>>(f_o, 0);
    k_trans_ds  <<<dim3(HR, BB), 256>>>(b_o, 1);
    k_trans_full<<<dim3(HH, BB), 256>>>(b_o);
    k_bnorm     <<<BB, 1024>>>();
    k_valid     <<<BB, 1024>>>(mask_o);
    k_conv_planes<<<BB * LL * CC / 256, 256>>>();
    k_biT       <<<dim3(16, 9, BB), 256>>>();
    // GEMM1 (reduced): G = bt * ft^T (K=128) -> g_Sf
    k_mma       <<<dim3(8, 8, BB), 256, K_MMA_SMEM>>>(0);
    // S assembly: 9-tap shift sum of G with 1/nrm -> g_S
    k_sassy     <<<dim3(4, LL, BB), 256>>>();
    // fuse: g_S -> g_Sf -> g_S (coalesced passes)
    k_fuse_pass <<<dim3(32, BB), 256>>>(0);
    k_fuse_pass <<<dim3(32, BB), 256>>>(1);
    // softmax: reads fused g_S, writes score^T planes (g_A2h/l)
    k_softmax   <<<dim3(8, BB), 128>>>();
    // GEMM2: R[q][k'] = sum_p score[p][q] * bi[p][k'] -> g_R
    k_mma       <<<dim3(9, 8, BB), 256, K_MMA_SMEM>>>(1);
    k_out       <<<dim3(HH, BB), CC>>>(out);
}

// round 14
// speedup vs baseline: 6.0138x; 2.3830x over previous
#include <cuda_runtime.h>
#include <cuda_bf16.h>
#include <math.h>
#include <stdint.h>

// Problem constants
#define BB   16
#define CC   128
#define HH   64
#define WW   64
#define HR   32
#define WR   32
#define LL   1024          // HR*WR
#define KK   1152          // CC*9

// ---------------- scratch (device globals; only referenced from device code) --
__device__ float g_ft  [BB * HR * WR * CC];
__device__ float g_bt  [BB * HR * WR * CC];
__device__ float g_bot [BB * HH * WW * CC];
__device__ float g_bnorm[BB * LL];
__device__ int   g_plist[BB * LL];                   // compact valid-p lists
__device__ int   g_vcount[BB];                       // valid counts per batch
__device__ float g_S  [BB * LL * LL];                // assembled S -> fused S
__device__ float g_Sf [BB * LL * LL];                // raw G / fuse stage 1
__device__ float g_R  [BB * LL * KK];
// bf16 split operand planes
__device__ __nv_bfloat16 g_A1h[BB * LL * CC];        // bt hi   [b][u][c]
__device__ __nv_bfloat16 g_A1l[BB * LL * CC];        // bt lo
__device__ __nv_bfloat16 g_B1h[BB * LL * CC];        // ft hi   [b][v][c]
__device__ __nv_bfloat16 g_B1l[BB * LL * CC];        // ft lo
__device__ __nv_bfloat16 g_A2h[BB * LL * LL];        // compact score^T hi [b][q][vi] (stride LL)
__device__ __nv_bfloat16 g_A2l[BB * LL * LL];        // compact score^T lo
__device__ __nv_bfloat16 g_B2h[BB * KK * LL];        // compact bi^T hi  [b][k'][vi] (stride LL)
__device__ __nv_bfloat16 g_B2l[BB * KK * LL];        // compact bi^T lo

// ---------------- PTX helpers (all baseline sm_80+, legal on compute_103) ----
__device__ __forceinline__ uint32_t smem_u32(const void* p) {
    uint32_t a;
    asm("{ .reg .u64 t; cvta.to.shared.u64 t, %1; cvt.u32.u64 %0, t; }" : "=r"(a) : "l"(p));
    return a;
}

#define CP_ASYNC16(dst, src) \
    asm volatile("cp.async.cg.shared.global [%0], [%1], 16;" :: "r"(dst), "l"(src))
#define CP_COMMIT() asm volatile("cp.async.commit_group;" ::: "memory")
#define CP_WAIT(n)  asm volatile("cp.async.wait_group %0;" :: "n"(n) : "memory")

#define LDSM_X4(r0, r1, r2, r3, addr) \
    asm volatile("ldmatrix.sync.aligned.m8n8.x4.shared.b16 {%0,%1,%2,%3}, [%4];" \
        : "=r"(r0), "=r"(r1), "=r"(r2), "=r"(r3) : "r"(addr))

#define MMA_BF16(c, a, b0, b1) \
    asm volatile("mma.sync.aligned.m16n8k16.row.col.f32.bf16.bf16.f32 " \
        "{%0,%1,%2,%3}, {%4,%5,%6,%7}, {%8,%9}, {%0,%1,%2,%3};" \
        : "+f"((c)[0]), "+f"((c)[1]), "+f"((c)[2]), "+f"((c)[3]) \
        : "r"((a)[0]), "r"((a)[1]), "r"((a)[2]), "r"((a)[3]), "r"(b0), "r"(b1))

// ---------------- transpose to channel-last ----------------------------------
__global__ void k_trans_ds(const float* __restrict__ src, int sel) {
    __shared__ float stage[HR * 129];
    const int y = blockIdx.x;
    const int b = blockIdx.y;
    float* dst = sel ? g_bt : g_ft;
    const int tid = threadIdx.x;
    for (int i = tid; i < HR * CC; i += 256) {
        int x = i & 31;
        int c = i >> 5;
        stage[x * 129 + c] = src[(((size_t)b * CC + c) * HH + 2 * y) * WW + 2 * x];
    }
    __syncthreads();
    for (int i = tid; i < HR * CC; i += 256) {
        int c = i & 127;
        int x = i >> 7;
        dst[(((size_t)b * HR + y) * WR + x) * CC + c] = stage[x * 129 + c];
    }
}

__global__ void k_trans_full(const float* __restrict__ src) {
    __shared__ float stage[WW * 129];
    const int y = blockIdx.x;
    const int b = blockIdx.y;
    const int tid = threadIdx.x;
    for (int i = tid; i < WW * CC; i += 256) {
        int x = i & 63;
        int c = i >> 6;
        stage[x * 129 + c] = src[(((size_t)b * CC + c) * HH + y) * WW + x];
    }
    __syncthreads();
    for (int i = tid; i < WW * CC; i += 256) {
        int c = i & 127;
        int x = i >> 7;
        g_bot[(((size_t)b * HH + y) * WW + x) * CC + c] = stage[x * 129 + c];
    }
}

// ---------------- bnorm -------------------------------------------------------
__global__ void k_bnorm() {
    __shared__ float ss[LL];
    const int b = blockIdx.x;
    const int tid = threadIdx.x;
    const int warp = tid >> 5, lane = tid & 31;
    for (int pos = warp; pos < LL; pos += 32) {
        float4 v = *(const float4*)&g_bt[((size_t)b * LL + pos) * CC + lane * 4];
        float s = v.x * v.x + v.y * v.y + v.z * v.z + v.w * v.w;
        #pragma unroll
        for (int o = 16; o; o >>= 1) s += __shfl_xor_sync(0xffffffffu, s, o);
        if (lane == 0) ss[pos] = s;
    }
    __syncthreads();
    const int p = tid, py = p >> 5, px = p & 31;
    float sum = 0.f;
    #pragma unroll
    for (int i = 0; i < 3; i++)
        #pragma unroll
        for (int j = 0; j < 3; j++) {
            int y = py + i - 1, x = px + j - 1;
            if ((unsigned)y < HR && (unsigned)x < WR) sum += ss[y * WR + x];
        }
    g_bnorm[b * LL + p] = fmaxf(sqrtf(sum), 1e-4f);
}

// ---------------- valid mask -> deterministic compact list --------------------
__global__ void k_valid_scan(const float* __restrict__ mask_o) {
    __shared__ float md[LL];
    __shared__ int sc[LL];
    const int b = blockIdx.x;
    const int tid = threadIdx.x;
    md[tid] = mask_o[(size_t)b * HH * WW + (2 * (tid >> 5)) * WW + 2 * (tid & 31)];
    __syncthreads();
    const int py = tid >> 5, px = tid & 31;
    float sum = 0.f;
    #pragma unroll
    for (int i = 0; i < 3; i++)
        #pragma unroll
        for (int j = 0; j < 3; j++) {
            int y = py + i - 1, x = px + j - 1;
            if ((unsigned)y < HR && (unsigned)x < WR) sum += md[y * WR + x];
        }
    const int flag = (sum == 0.f) ? 1 : 0;
    sc[tid] = flag;
    __syncthreads();
    for (int off = 1; off < LL; off <<= 1) {
        int v = sc[tid];
        if (tid >= off) v += sc[tid - off];
        __syncthreads();
        sc[tid] = v;
        __syncthreads();
    }
    if (flag) g_plist[b * LL + sc[tid] - 1] = tid;
    if (tid == LL - 1) g_vcount[b] = sc[LL - 1];
}

// ---------------- bf16 hi/lo planes of ft/bt ---------------------------------
__global__ void k_conv_planes() {
    const size_t i = (size_t)blockIdx.x * 256 + threadIdx.x;   // over BB*LL*CC
    const float bv = g_bt[i], fv = g_ft[i];
    __nv_bfloat16 h = __float2bfloat16(bv);
    g_A1h[i] = h;
    g_A1l[i] = __float2bfloat16(bv - __bfloat162float(h));
    h = __float2bfloat16(fv);
    g_B1h[i] = h;
    g_B1l[i] = __float2bfloat16(fv - __bfloat162float(h));
}

// ---------------- compact bi^T planes: [b][k'][vi], vi < Kceil ----------------
__global__ void k_biTc() {
    const int t = blockIdx.x;      // ij (0..8)
    const int b = blockIdx.y;
    const int i = t / 3, j = t % 3;
    const int c = threadIdx.x;     // 128
    const int V = g_vcount[b];
    const int Kceil = (V + 31) & ~31;
    for (int vi = 0; vi < Kceil; vi++) {
        float v = 0.f;
        if (vi < V) {
            const int p = g_plist[b * LL + vi];
            const int y = 2 * (p >> 5) + i - 1, x = 2 * (p & 31) + j - 1;
            if ((unsigned)y < HH && (unsigned)x < WW)
                v = g_bot[(((size_t)b * HH + y) * WW + x) * CC + c];
        }
        const size_t o = (((size_t)b * KK + t * 128 + c) << 10) + vi;
        __nv_bfloat16 h = __float2bfloat16(v);
        g_B2h[o] = h;
        g_B2l[o] = __float2bfloat16(v - __bfloat162float(h));
    }
}

// ---------------- mma.sync split-bf16 GEMM ------------------------------------
// sel 0: G[u][v]  = sum_c bt[u][c]*ft[v][c]           (M=N=1024, K=128)  -> g_Sf
// sel 1: R[q][k'] = sum_vi scoreC[q][vi]*biC[k'][vi]  (M=1024, N=1152, K=Kceil dyn)
#define SM_STRIDE 40                 // padded bf16 elems per smem row
#define TILE_BYTES (128 * SM_STRIDE * 2)   // 10240
#define STAGE_BYTES (4 * TILE_BYTES)       // Ah, Al, Bh, Bl
#define K_MMA_SMEM (2 * STAGE_BYTES)       // 81920

__global__ void __launch_bounds__(256) k_mma(int sel) {
    extern __shared__ __align__(16) char smem[];
    const uint32_t sbase = smem_u32(smem);
    const int tid = threadIdx.x;
    const int lane = tid & 31, wid = tid >> 5;
    const int wm = (wid & 3) * 32;       // warp m offset in tile
    const int wn = (wid >> 2) * 64;      // warp n offset in tile
    const int b = blockIdx.z, my = blockIdx.y, nx = blockIdx.x;

    const int stride = sel ? LL : CC;    // operand row stride
    const int iters = sel ? ((g_vcount[b] + 31) >> 5) : (CC / 32);
    const int Ncols = sel ? KK : LL;     // C row stride
    const __nv_bfloat16* Ah = sel ? g_A2h + ((size_t)b << 20) : g_A1h + (size_t)b * LL * CC;
    const __nv_bfloat16* Al = sel ? g_A2l + ((size_t)b << 20) : g_A1l + (size_t)b * LL * CC;
    const __nv_bfloat16* Bh = sel ? g_B2h + (size_t)b * KK * LL : g_B1h + (size_t)b * LL * CC;
    const __nv_bfloat16* Bl = sel ? g_B2l + (size_t)b * KK * LL : g_B1l + (size_t)b * LL * CC;
    float* Cb = sel ? g_R + (size_t)b * LL * KK : g_Sf + ((size_t)b << 20);

    float acc[2][8][4];
    #pragma unroll
    for (int mt = 0; mt < 2; mt++)
        #pragma unroll
        for (int nt = 0; nt < 8; nt++)
            #pragma unroll
            for (int u = 0; u < 4; u++) acc[mt][nt][u] = 0.f;

    // ---- stage loader ----
    auto load_stage = [&](int kt, int buf) {
        const uint32_t sdst = sbase + buf * STAGE_BYTES;
        #pragma unroll
        for (int t = 0; t < 4; t++) {
            const __nv_bfloat16* src = (t == 0) ? Ah : (t == 1) ? Al : (t == 2) ? Bh : Bl;
            const int rowbase = (t < 2) ? my * 128 : nx * 128;
            #pragma unroll
            for (int u = 0; u < 2; u++) {
                const int id = tid * 2 + u;             // 0..511
                const int r = id >> 2, c4 = id & 3;     // row, 16B-chunk (8 elems)
                const uint32_t d = sdst + t * TILE_BYTES + (r * SM_STRIDE + c4 * 8) * 2;
                const __nv_bfloat16* s = src + (size_t)(rowbase + r) * stride + kt + c4 * 8;
                CP_ASYNC16(d, s);
            }
        }
        CP_COMMIT();
    };

    if (iters > 0) {
        load_stage(0, 0);

        for (int i = 0; i < iters; i++) {
            const int buf = i & 1;
            if (i + 1 < iters) load_stage((i + 1) * 32, buf ^ 1);
            if (i + 1 < iters) { CP_WAIT(1); } else { CP_WAIT(0); }
            __syncthreads();

            const uint32_t sa = sbase + buf * STAGE_BYTES;
            const uint32_t pAh = sa, pAl = sa + TILE_BYTES;
            const uint32_t pBh = sa + 2 * TILE_BYTES, pBl = sa + 3 * TILE_BYTES;

            #pragma unroll
            for (int ks = 0; ks < 2; ks++) {
                uint32_t ah[2][4], al[2][4];
                #pragma unroll
                for (int mt = 0; mt < 2; mt++) {
                    const int r = wm + mt * 16 + (lane & 15);
                    const uint32_t off = (uint32_t)(r * SM_STRIDE + ks * 16 + ((lane >> 4) << 3)) * 2;
                    LDSM_X4(ah[mt][0], ah[mt][1], ah[mt][2], ah[mt][3], pAh + off);
                    LDSM_X4(al[mt][0], al[mt][1], al[mt][2], al[mt][3], pAl + off);
                }
                #pragma unroll
                for (int np = 0; np < 4; np++) {
                    const int rn = wn + np * 16 + (lane & 7) + ((lane >> 4) << 3);
                    const uint32_t off = (uint32_t)(rn * SM_STRIDE + ks * 16 + (((lane >> 3) & 1) << 3)) * 2;
                    uint32_t bh4[4], bl4[4];
                    LDSM_X4(bh4[0], bh4[1], bh4[2], bh4[3], pBh + off);
                    LDSM_X4(bl4[0], bl4[1], bl4[2], bl4[3], pBl + off);
                    #pragma unroll
                    for (int h2 = 0; h2 < 2; h2++) {
                        const int nt = np * 2 + h2;
                        #pragma unroll
                        for (int mt = 0; mt < 2; mt++) {
                            MMA_BF16(acc[mt][nt], ah[mt], bh4[h2 * 2], bh4[h2 * 2 + 1]);
                            MMA_BF16(acc[mt][nt], ah[mt], bl4[h2 * 2], bl4[h2 * 2 + 1]);
                            MMA_BF16(acc[mt][nt], al[mt], bh4[h2 * 2], bh4[h2 * 2 + 1]);
                        }
                    }
                }
            }
            __syncthreads();
        }
    }

    // ---- store C ----
    #pragma unroll
    for (int mt = 0; mt < 2; mt++) {
        const int row0 = my * 128 + wm + mt * 16 + (lane >> 2);
        #pragma unroll
        for (int nt = 0; nt < 8; nt++) {
            const int col = nx * 128 + wn + nt * 8 + (lane & 3) * 2;
            float* c0 = Cb + (size_t)row0 * Ncols + col;
            float* c1 = Cb + (size_t)(row0 + 8) * Ncols + col;
            c0[0] = acc[mt][nt][0]; c0[1] = acc[mt][nt][1];
            c1[0] = acc[mt][nt][2]; c1[1] = acc[mt][nt][3];
        }
    }
}

// ---------------- S assembly: 9-tap 2D shift-sum of G, scaled by 1/nrm --------
__global__ void k_sassy() {
    const int b = blockIdx.z;
    const int p = blockIdx.y;
    const int q = blockIdx.x * 256 + threadIdx.x;
    const int py = p >> 5, px = p & 31;
    const int qy = q >> 5, qx = q & 31;
    const float inv = 1.f / g_bnorm[b * LL + p];
    const float* G = g_Sf + ((size_t)b << 20);
    float acc = 0.f;
    #pragma unroll
    for (int di = -1; di <= 1; di++) {
        if ((unsigned)(py + di) >= HR || (unsigned)(qy + di) >= HR) continue;
        #pragma unroll
        for (int dj = -1; dj <= 1; dj++) {
            if ((unsigned)(px + dj) >= WR || (unsigned)(qx + dj) >= WR) continue;
            const int s = di * 32 + dj;
            acc += G[((size_t)(p + s) << 10) + (q + s)];
        }
    }
    g_S[((size_t)b << 20) + ((size_t)p << 10) + q] = acc * inv;
}

// ---------------- fuse: coalesced diag-fuse passes ----------------------------
// dst[tsw(p)][tsw(q)] = sum_{d=-1..1} src[p+d][q+d]
__device__ __forceinline__ int tsw(int x) { return ((x & 31) << 5) | (x >> 5); }

__global__ void k_fuse_pass(int stage) {
    __shared__ float vbuf[LL + 32];       // padded: idx = q + (q>>5)
    const int ph = blockIdx.x;            // 0..31
    const int b  = blockIdx.y;
    const float* src = (stage ? g_Sf : g_S) + ((size_t)b << 20);
    float*       dst = (stage ? g_S  : g_Sf) + ((size_t)b << 20);
    const int tid = threadIdx.x;          // 256
    for (int pl = 0; pl < 32; pl++) {
        const int p = ph * 32 + pl;
        #pragma unroll
        for (int k = 0; k < 4; k++) {
            const int q = tid + k * 256;
            float acc = 0.f;
            #pragma unroll
            for (int d = -1; d <= 1; d++) {
                const int pp = p + d, qq = q + d;
                if ((unsigned)pp < LL && (unsigned)qq < LL)
                    acc += src[((size_t)pp << 10) + qq];
            }
            vbuf[q + (q >> 5)] = acc;
        }
        __syncthreads();
        const int rp = pl * 32 + ph;      // tsw(p)
        #pragma unroll
        for (int k = 0; k < 4; k++) {
            const int cp = tid + k * 256;
            const int q = ((cp & 31) << 5) | (cp >> 5);   // tsw(cp)
            dst[((size_t)rp << 10) + cp] = vbuf[q + (q >> 5)];
        }
        __syncthreads();
    }
}

// ---------------- sparse softmax over p; writes compact score^T planes -------
// logits: l_p = 10*S[p,q] for valid p, exactly 0 for the other (LL-V) rows.
__global__ void k_softmax_c() {
    const int qt = blockIdx.x;     // 0..7
    const int b  = blockIdx.y;
    const int q  = qt * 128 + threadIdx.x;
    const int V = g_vcount[b];
    const int Kceil = (V + 31) & ~31;
    const float* S = g_S + ((size_t)b << 20);
    float mx = (V < LL) ? 0.f : -1e30f;
    for (int vi = 0; vi < V; vi++) {
        const int p = g_plist[b * LL + vi];
        mx = fmaxf(mx, 10.f * S[((size_t)p << 10) + q]);
    }
    float sum = (V < LL) ? (float)(LL - V) * expf(0.f - mx) : 0.f;
    for (int vi = 0; vi < V; vi++) {
        const int p = g_plist[b * LL + vi];
        sum += expf(10.f * S[((size_t)p << 10) + q] - mx);
    }
    const float inv = 1.f / sum;
    const size_t rowb = (((size_t)b << 10) + q) << 10;
    for (int vi = 0; vi < Kceil; vi++) {
        float v = 0.f;
        if (vi < V) {
            const int p = g_plist[b * LL + vi];
            v = expf(10.f * S[((size_t)p << 10) + q] - mx) * inv;
        }
        __nv_bfloat16 h = __float2bfloat16(v);
        g_A2h[rowb + vi] = h;
        g_A2l[rowb + vi] = __float2bfloat16(v - __bfloat162float(h));
    }
}

// ---------------- transposed-conv gather from R -------------------------------
__global__ void k_out(float* __restrict__ out) {
    const int y = blockIdx.x;
    const int b = blockIdx.y;
    const int c = threadIdx.x;
    int qylo = (y - 1) < 0 ? 0 : (y - 1) >> 1;
    int qyhi = (y + 1) >> 1; if (qyhi > 31) qyhi = 31;
    for (int x = 0; x < WW; x++) {
        int qxlo = (x - 1) < 0 ? 0 : (x - 1) >> 1;
        int qxhi = (x + 1) >> 1; if (qxhi > 31) qxhi = 31;
        float acc = 0.f;
        for (int qy = qylo; qy <= qyhi; qy++) {
            const int i = y - 2 * qy + 1;
            if (i < 0 || i > 2) continue;
            for (int qx = qxlo; qx <= qxhi; qx++) {
                const int j = x - 2 * qx + 1;
                if (j < 0 || j > 2) continue;
                const int q = qy * WR + qx;
                acc += g_R[(((size_t)b * LL + q) * 9 + i * 3 + j) * CC + c];
            }
        }
        out[(((size_t)b * CC + c) * HH + y) * WW + x] = acc * 0.25f;
    }
}

// ---------------- orchestration ----------------------------------------------
extern "C" void kernel_launch(void* const* d_in, const int* in_sizes, int n_in,
                              void* d_out, int out_size) {
    const float* big[2] = {nullptr, nullptr};
    const float* mask_o = nullptr;
    int nb = 0;
    for (int i = 0; i < n_in && i < 3; i++) {
        if (in_sizes[i] == BB * 1 * HH * WW) {
            mask_o = (const float*)d_in[i];
        } else if (nb < 2) {
            big[nb++] = (const float*)d_in[i];
        }
    }
    const float* f_o = big[0] ? big[0] : (const float*)d_in[0];
    const float* b_o = big[1] ? big[1] : (const float*)d_in[1];
    if (!mask_o) mask_o = (const float*)d_in[2];
    float* out = (float*)d_out;

    cudaFuncSetAttribute(k_mma, cudaFuncAttributeMaxDynamicSharedMemorySize, K_MMA_SMEM);

    k_trans_ds  <<<dim3(HR, BB), 256>>>(f_o, 0);
    k_trans_ds  <<<dim3(HR, BB), 256>>>(b_o, 1);
    k_trans_full<<<dim3(HH, BB), 256>>>(b_o);
    k_bnorm     <<<BB, 1024>>>();
    k_valid_scan<<<BB, 1024>>>(mask_o);
    k_conv_planes<<<BB * LL * CC / 256, 256>>>();
    k_biTc      <<<dim3(9, BB), 128>>>();
    // GEMM1 (reduced): G = bt * ft^T (K=128) -> g_Sf
    k_mma       <<<dim3(8, 8, BB), 256, K_MMA_SMEM>>>(0);
    // S assembly: 9-tap shift sum of G with 1/nrm -> g_S
    k_sassy     <<<dim3(4, LL, BB), 256>>>();
    // fuse: g_S -> g_Sf -> g_S (coalesced passes)
    k_fuse_pass <<<dim3(32, BB), 256>>>(0);
    k_fuse_pass <<<dim3(32, BB), 256>>>(1);
    // sparse softmax: reads V rows of fused g_S, writes compact score^T planes
    k_softmax_c <<<dim3(8, BB), 128>>>();
    // GEMM2 (sparse K): R[q][k'] = sum_vi scoreC[q][vi] * biC[k'][vi] -> g_R
    k_mma       <<<dim3(9, 8, BB), 256, K_MMA_SMEM>>>(1);
    k_out       <<<dim3(HH, BB), CC>>>(out);
}

// round 15
// speedup vs baseline: 9.2298x; 1.5348x over previous
#include <cuda_runtime.h>
#include <cuda_bf16.h>
#include <math.h>
#include <stdint.h>

// Problem constants
#define BB   16
#define CC   128
#define HH   64
#define WW   64
#define HR   32
#define WR   32
#define LL   1024          // HR*WR
#define KK   1152          // CC*9

// ---------------- scratch (device globals; only referenced from device code) --
__device__ float g_ft  [BB * HR * WR * CC];
__device__ float g_bt  [BB * HR * WR * CC];
__device__ float g_bot [BB * HH * WW * CC];
__device__ float g_bnorm[BB * LL];
__device__ int   g_plist[BB * LL];                   // compact valid-p lists
__device__ int   g_vcount[BB];                       // valid counts per batch
__device__ float g_S  [BB * LL * LL];                // compact fused Sv [b][vi][q]
__device__ float g_Sf [BB * LL * LL];                // raw G
__device__ float g_R  [BB * LL * KK];
// bf16 split operand planes
__device__ __nv_bfloat16 g_A1h[BB * LL * CC];        // bt hi   [b][u][c]
__device__ __nv_bfloat16 g_A1l[BB * LL * CC];        // bt lo
__device__ __nv_bfloat16 g_B1h[BB * LL * CC];        // ft hi   [b][v][c]
__device__ __nv_bfloat16 g_B1l[BB * LL * CC];        // ft lo
__device__ __nv_bfloat16 g_A2h[BB * LL * LL];        // compact score^T hi [b][q][vi] (stride LL)
__device__ __nv_bfloat16 g_A2l[BB * LL * LL];        // compact score^T lo
__device__ __nv_bfloat16 g_B2h[BB * KK * LL];        // compact bi^T hi  [b][k'][vi] (stride LL)
__device__ __nv_bfloat16 g_B2l[BB * KK * LL];        // compact bi^T lo

// ---------------- PTX helpers (all baseline sm_80+, legal on compute_103) ----
__device__ __forceinline__ uint32_t smem_u32(const void* p) {
    uint32_t a;
    asm("{ .reg .u64 t; cvta.to.shared.u64 t, %1; cvt.u32.u64 %0, t; }" : "=r"(a) : "l"(p));
    return a;
}

#define CP_ASYNC16(dst, src) \
    asm volatile("cp.async.cg.shared.global [%0], [%1], 16;" :: "r"(dst), "l"(src))
#define CP_COMMIT() asm volatile("cp.async.commit_group;" ::: "memory")
#define CP_WAIT(n)  asm volatile("cp.async.wait_group %0;" :: "n"(n) : "memory")

#define LDSM_X4(r0, r1, r2, r3, addr) \
    asm volatile("ldmatrix.sync.aligned.m8n8.x4.shared.b16 {%0,%1,%2,%3}, [%4];" \
        : "=r"(r0), "=r"(r1), "=r"(r2), "=r"(r3) : "r"(addr))

#define MMA_BF16(c, a, b0, b1) \
    asm volatile("mma.sync.aligned.m16n8k16.row.col.f32.bf16.bf16.f32 " \
        "{%0,%1,%2,%3}, {%4,%5,%6,%7}, {%8,%9}, {%0,%1,%2,%3};" \
        : "+f"((c)[0]), "+f"((c)[1]), "+f"((c)[2]), "+f"((c)[3]) \
        : "r"((a)[0]), "r"((a)[1]), "r"((a)[2]), "r"((a)[3]), "r"(b0), "r"(b1))

// ---------------- transpose to channel-last ----------------------------------
__global__ void k_trans_ds(const float* __restrict__ src, int sel) {
    __shared__ float stage[HR * 129];
    const int y = blockIdx.x;
    const int b = blockIdx.y;
    float* dst = sel ? g_bt : g_ft;
    const int tid = threadIdx.x;
    for (int i = tid; i < HR * CC; i += 256) {
        int x = i & 31;
        int c = i >> 5;
        stage[x * 129 + c] = src[(((size_t)b * CC + c) * HH + 2 * y) * WW + 2 * x];
    }
    __syncthreads();
    for (int i = tid; i < HR * CC; i += 256) {
        int c = i & 127;
        int x = i >> 7;
        dst[(((size_t)b * HR + y) * WR + x) * CC + c] = stage[x * 129 + c];
    }
}

__global__ void k_trans_full(const float* __restrict__ src) {
    __shared__ float stage[WW * 129];
    const int y = blockIdx.x;
    const int b = blockIdx.y;
    const int tid = threadIdx.x;
    for (int i = tid; i < WW * CC; i += 256) {
        int x = i & 63;
        int c = i >> 6;
        stage[x * 129 + c] = src[(((size_t)b * CC + c) * HH + y) * WW + x];
    }
    __syncthreads();
    for (int i = tid; i < WW * CC; i += 256) {
        int c = i & 127;
        int x = i >> 7;
        g_bot[(((size_t)b * HH + y) * WW + x) * CC + c] = stage[x * 129 + c];
    }
}

// ---------------- bnorm -------------------------------------------------------
__global__ void k_bnorm() {
    __shared__ float ss[LL];
    const int b = blockIdx.x;
    const int tid = threadIdx.x;
    const int warp = tid >> 5, lane = tid & 31;
    for (int pos = warp; pos < LL; pos += 32) {
        float4 v = *(const float4*)&g_bt[((size_t)b * LL + pos) * CC + lane * 4];
        float s = v.x * v.x + v.y * v.y + v.z * v.z + v.w * v.w;
        #pragma unroll
        for (int o = 16; o; o >>= 1) s += __shfl_xor_sync(0xffffffffu, s, o);
        if (lane == 0) ss[pos] = s;
    }
    __syncthreads();
    const int p = tid, py = p >> 5, px = p & 31;
    float sum = 0.f;
    #pragma unroll
    for (int i = 0; i < 3; i++)
        #pragma unroll
        for (int j = 0; j < 3; j++) {
            int y = py + i - 1, x = px + j - 1;
            if ((unsigned)y < HR && (unsigned)x < WR) sum += ss[y * WR + x];
        }
    g_bnorm[b * LL + p] = fmaxf(sqrtf(sum), 1e-4f);
}

// ---------------- valid mask -> deterministic compact list --------------------
__global__ void k_valid_scan(const float* __restrict__ mask_o) {
    __shared__ float md[LL];
    __shared__ int sc[LL];
    const int b = blockIdx.x;
    const int tid = threadIdx.x;
    md[tid] = mask_o[(size_t)b * HH * WW + (2 * (tid >> 5)) * WW + 2 * (tid & 31)];
    __syncthreads();
    const int py = tid >> 5, px = tid & 31;
    float sum = 0.f;
    #pragma unroll
    for (int i = 0; i < 3; i++)
        #pragma unroll
        for (int j = 0; j < 3; j++) {
            int y = py + i - 1, x = px + j - 1;
            if ((unsigned)y < HR && (unsigned)x < WR) sum += md[y * WR + x];
        }
    const int flag = (sum == 0.f) ? 1 : 0;
    sc[tid] = flag;
    __syncthreads();
    for (int off = 1; off < LL; off <<= 1) {
        int v = sc[tid];
        if (tid >= off) v += sc[tid - off];
        __syncthreads();
        sc[tid] = v;
        __syncthreads();
    }
    if (flag) g_plist[b * LL + sc[tid] - 1] = tid;
    if (tid == LL - 1) g_vcount[b] = sc[LL - 1];
}

// ---------------- bf16 hi/lo planes of ft/bt ---------------------------------
__global__ void k_conv_planes() {
    const size_t i = (size_t)blockIdx.x * 256 + threadIdx.x;   // over BB*LL*CC
    const float bv = g_bt[i], fv = g_ft[i];
    __nv_bfloat16 h = __float2bfloat16(bv);
    g_A1h[i] = h;
    g_A1l[i] = __float2bfloat16(bv - __bfloat162float(h));
    h = __float2bfloat16(fv);
    g_B1h[i] = h;
    g_B1l[i] = __float2bfloat16(fv - __bfloat162float(h));
}

// ---------------- compact bi^T planes: [b][k'][vi], vi < Kceil ----------------
__global__ void k_biTc() {
    const int t = blockIdx.x;      // ij (0..8)
    const int b = blockIdx.y;
    const int i = t / 3, j = t % 3;
    const int c = threadIdx.x;     // 128
    const int V = g_vcount[b];
    const int Kceil = (V + 31) & ~31;
    for (int vi = 0; vi < Kceil; vi++) {
        float v = 0.f;
        if (vi < V) {
            const int p = g_plist[b * LL + vi];
            const int y = 2 * (p >> 5) + i - 1, x = 2 * (p & 31) + j - 1;
            if ((unsigned)y < HH && (unsigned)x < WW)
                v = g_bot[(((size_t)b * HH + y) * WW + x) * CC + c];
        }
        const size_t o = (((size_t)b * KK + t * 128 + c) << 10) + vi;
        __nv_bfloat16 h = __float2bfloat16(v);
        g_B2h[o] = h;
        g_B2l[o] = __float2bfloat16(v - __bfloat162float(h));
    }
}

// ---------------- mma.sync split-bf16 GEMM ------------------------------------
// sel 0: G[u][v]  = sum_c bt[u][c]*ft[v][c]           (M=N=1024, K=128)  -> g_Sf
// sel 1: R[q][k'] = sum_vi scoreC[q][vi]*biC[k'][vi]  (M=1024, N=1152, K=Kceil dyn)
#define SM_STRIDE 40                 // padded bf16 elems per smem row
#define TILE_BYTES (128 * SM_STRIDE * 2)   // 10240
#define STAGE_BYTES (4 * TILE_BYTES)       // Ah, Al, Bh, Bl
#define K_MMA_SMEM (2 * STAGE_BYTES)       // 81920

__global__ void __launch_bounds__(256) k_mma(int sel) {
    extern __shared__ __align__(16) char smem[];
    const uint32_t sbase = smem_u32(smem);
    const int tid = threadIdx.x;
    const int lane = tid & 31, wid = tid >> 5;
    const int wm = (wid & 3) * 32;       // warp m offset in tile
    const int wn = (wid >> 2) * 64;      // warp n offset in tile
    const int b = blockIdx.z, my = blockIdx.y, nx = blockIdx.x;

    const int stride = sel ? LL : CC;    // operand row stride
    const int iters = sel ? ((g_vcount[b] + 31) >> 5) : (CC / 32);
    const int Ncols = sel ? KK : LL;     // C row stride
    const __nv_bfloat16* Ah = sel ? g_A2h + ((size_t)b << 20) : g_A1h + (size_t)b * LL * CC;
    const __nv_bfloat16* Al = sel ? g_A2l + ((size_t)b << 20) : g_A1l + (size_t)b * LL * CC;
    const __nv_bfloat16* Bh = sel ? g_B2h + (size_t)b * KK * LL : g_B1h + (size_t)b * LL * CC;
    const __nv_bfloat16* Bl = sel ? g_B2l + (size_t)b * KK * LL : g_B1l + (size_t)b * LL * CC;
    float* Cb = sel ? g_R + (size_t)b * LL * KK : g_Sf + ((size_t)b << 20);

    float acc[2][8][4];
    #pragma unroll
    for (int mt = 0; mt < 2; mt++)
        #pragma unroll
        for (int nt = 0; nt < 8; nt++)
            #pragma unroll
            for (int u = 0; u < 4; u++) acc[mt][nt][u] = 0.f;

    // ---- stage loader ----
    auto load_stage = [&](int kt, int buf) {
        const uint32_t sdst = sbase + buf * STAGE_BYTES;
        #pragma unroll
        for (int t = 0; t < 4; t++) {
            const __nv_bfloat16* src = (t == 0) ? Ah : (t == 1) ? Al : (t == 2) ? Bh : Bl;
            const int rowbase = (t < 2) ? my * 128 : nx * 128;
            #pragma unroll
            for (int u = 0; u < 2; u++) {
                const int id = tid * 2 + u;             // 0..511
                const int r = id >> 2, c4 = id & 3;     // row, 16B-chunk (8 elems)
                const uint32_t d = sdst + t * TILE_BYTES + (r * SM_STRIDE + c4 * 8) * 2;
                const __nv_bfloat16* s = src + (size_t)(rowbase + r) * stride + kt + c4 * 8;
                CP_ASYNC16(d, s);
            }
        }
        CP_COMMIT();
    };

    if (iters > 0) {
        load_stage(0, 0);

        for (int i = 0; i < iters; i++) {
            const int buf = i & 1;
            if (i + 1 < iters) load_stage((i + 1) * 32, buf ^ 1);
            if (i + 1 < iters) { CP_WAIT(1); } else { CP_WAIT(0); }
            __syncthreads();

            const uint32_t sa = sbase + buf * STAGE_BYTES;
            const uint32_t pAh = sa, pAl = sa + TILE_BYTES;
            const uint32_t pBh = sa + 2 * TILE_BYTES, pBl = sa + 3 * TILE_BYTES;

            #pragma unroll
            for (int ks = 0; ks < 2; ks++) {
                uint32_t ah[2][4], al[2][4];
                #pragma unroll
                for (int mt = 0; mt < 2; mt++) {
                    const int r = wm + mt * 16 + (lane & 15);
                    const uint32_t off = (uint32_t)(r * SM_STRIDE + ks * 16 + ((lane >> 4) << 3)) * 2;
                    LDSM_X4(ah[mt][0], ah[mt][1], ah[mt][2], ah[mt][3], pAh + off);
                    LDSM_X4(al[mt][0], al[mt][1], al[mt][2], al[mt][3], pAl + off);
                }
                #pragma unroll
                for (int np = 0; np < 4; np++) {
                    const int rn = wn + np * 16 + (lane & 7) + ((lane >> 4) << 3);
                    const uint32_t off = (uint32_t)(rn * SM_STRIDE + ks * 16 + (((lane >> 3) & 1) << 3)) * 2;
                    uint32_t bh4[4], bl4[4];
                    LDSM_X4(bh4[0], bh4[1], bh4[2], bh4[3], pBh + off);
                    LDSM_X4(bl4[0], bl4[1], bl4[2], bl4[3], pBl + off);
                    #pragma unroll
                    for (int h2 = 0; h2 < 2; h2++) {
                        const int nt = np * 2 + h2;
                        #pragma unroll
                        for (int mt = 0; mt < 2; mt++) {
                            MMA_BF16(acc[mt][nt], ah[mt], bh4[h2 * 2], bh4[h2 * 2 + 1]);
                            MMA_BF16(acc[mt][nt], ah[mt], bl4[h2 * 2], bl4[h2 * 2 + 1]);
                            MMA_BF16(acc[mt][nt], al[mt], bh4[h2 * 2], bh4[h2 * 2 + 1]);
                        }
                    }
                }
            }
            __syncthreads();
        }
    }

    // ---- store C ----
    #pragma unroll
    for (int mt = 0; mt < 2; mt++) {
        const int row0 = my * 128 + wm + mt * 16 + (lane >> 2);
        #pragma unroll
        for (int nt = 0; nt < 8; nt++) {
            const int col = nx * 128 + wn + nt * 8 + (lane & 3) * 2;
            float* c0 = Cb + (size_t)row0 * Ncols + col;
            float* c1 = Cb + (size_t)(row0 + 8) * Ncols + col;
            c0[0] = acc[mt][nt][0]; c0[1] = acc[mt][nt][1];
            c1[0] = acc[mt][nt][2]; c1[1] = acc[mt][nt][3];
        }
    }
}

// ---------------- sparse fused-S gather: only the V valid rows ----------------
// fused[p][q] = sum_{d2} sum_{d1} Sraw[tsw(tsw(p)+d2)+d1][tsw(tsw(q)+d2)+d1]
// Sraw[A][C]  = (1/nrm_A) * sum_{di,dj} G[A+32di+dj][C+32di+dj]  (2D bounds)
// Output: compact Sv[b][vi][q] stored in g_S (stride LL).
__device__ __forceinline__ int tsw(int x) { return ((x & 31) << 5) | (x >> 5); }

__global__ void k_fused_sparse() {
    const int b = blockIdx.z;
    const int V = g_vcount[b];
    const int q = blockIdx.x * 256 + threadIdx.x;
    const float* G = g_Sf + ((size_t)b << 20);
    float* Sv = g_S + ((size_t)b << 20);
    const int tq = tsw(q);
    for (int vi = blockIdx.y; vi < V; vi += 64) {
        const int p = g_plist[b * LL + vi];
        const int tp = tsw(p);
        float acc = 0.f;
        #pragma unroll
        for (int d2 = -1; d2 <= 1; d2++) {
            const int s = tp + d2, t = tq + d2;
            if ((unsigned)s >= LL || (unsigned)t >= LL) continue;
            const int ss_ = tsw(s), tt = tsw(t);
            #pragma unroll
            for (int d1 = -1; d1 <= 1; d1++) {
                const int A = ss_ + d1, C = tt + d1;
                if ((unsigned)A >= LL || (unsigned)C >= LL) continue;
                const float inv = 1.f / g_bnorm[b * LL + A];
                const int Ay = A >> 5, Ax = A & 31, Cy = C >> 5, Cx = C & 31;
                float sub = 0.f;
                #pragma unroll
                for (int di = -1; di <= 1; di++) {
                    if ((unsigned)(Ay + di) >= HR || (unsigned)(Cy + di) >= HR) continue;
                    #pragma unroll
                    for (int dj = -1; dj <= 1; dj++) {
                        if ((unsigned)(Ax + dj) >= WR || (unsigned)(Cx + dj) >= WR) continue;
                        const int sh = di * 32 + dj;
                        sub += G[((size_t)(A + sh) << 10) + (C + sh)];
                    }
                }
                acc += inv * sub;
            }
        }
        Sv[((size_t)vi << 10) + q] = acc;
    }
}

// ---------------- sparse softmax over p; writes compact score^T planes -------
// logits: l_vi = 10*Sv[vi][q] for valid rows, exactly 0 for the (LL-V) others.
__global__ void k_softmax_c() {
    const int qt = blockIdx.x;     // 0..7
    const int b  = blockIdx.y;
    const int q  = qt * 128 + threadIdx.x;
    const int V = g_vcount[b];
    const int Kceil = (V + 31) & ~31;
    const float* Sv = g_S + ((size_t)b << 20);
    float mx = (V < LL) ? 0.f : -1e30f;
    for (int vi = 0; vi < V; vi++)
        mx = fmaxf(mx, 10.f * Sv[((size_t)vi << 10) + q]);
    float sum = (V < LL) ? (float)(LL - V) * expf(0.f - mx) : 0.f;
    for (int vi = 0; vi < V; vi++)
        sum += expf(10.f * Sv[((size_t)vi << 10) + q] - mx);
    const float inv = 1.f / sum;
    const size_t rowb = (((size_t)b << 10) + q) << 10;
    for (int vi = 0; vi < Kceil; vi++) {
        float v = 0.f;
        if (vi < V)
            v = expf(10.f * Sv[((size_t)vi << 10) + q] - mx) * inv;
        __nv_bfloat16 h = __float2bfloat16(v);
        g_A2h[rowb + vi] = h;
        g_A2l[rowb + vi] = __float2bfloat16(v - __bfloat162float(h));
    }
}

// ---------------- transposed-conv gather from R -------------------------------
__global__ void k_out(float* __restrict__ out) {
    const int y = blockIdx.x;
    const int b = blockIdx.y;
    const int c = threadIdx.x;
    int qylo = (y - 1) < 0 ? 0 : (y - 1) >> 1;
    int qyhi = (y + 1) >> 1; if (qyhi > 31) qyhi = 31;
    for (int x = 0; x < WW; x++) {
        int qxlo = (x - 1) < 0 ? 0 : (x - 1) >> 1;
        int qxhi = (x + 1) >> 1; if (qxhi > 31) qxhi = 31;
        float acc = 0.f;
        for (int qy = qylo; qy <= qyhi; qy++) {
            const int i = y - 2 * qy + 1;
            if (i < 0 || i > 2) continue;
            for (int qx = qxlo; qx <= qxhi; qx++) {
                const int j = x - 2 * qx + 1;
                if (j < 0 || j > 2) continue;
                const int q = qy * WR + qx;
                acc += g_R[(((size_t)b * LL + q) * 9 + i * 3 + j) * CC + c];
            }
        }
        out[(((size_t)b * CC + c) * HH + y) * WW + x] = acc * 0.25f;
    }
}

// ---------------- orchestration ----------------------------------------------
extern "C" void kernel_launch(void* const* d_in, const int* in_sizes, int n_in,
                              void* d_out, int out_size) {
    const float* big[2] = {nullptr, nullptr};
    const float* mask_o = nullptr;
    int nb = 0;
    for (int i = 0; i < n_in && i < 3; i++) {
        if (in_sizes[i] == BB * 1 * HH * WW) {
            mask_o = (const float*)d_in[i];
        } else if (nb < 2) {
            big[nb++] = (const float*)d_in[i];
        }
    }
    const float* f_o = big[0] ? big[0] : (const float*)d_in[0];
    const float* b_o = big[1] ? big[1] : (const float*)d_in[1];
    if (!mask_o) mask_o = (const float*)d_in[2];
    float* out = (float*)d_out;

    cudaFuncSetAttribute(k_mma, cudaFuncAttributeMaxDynamicSharedMemorySize, K_MMA_SMEM);

    k_trans_ds  <<<dim3(HR, BB), 256>>>(f_o, 0);
    k_trans_ds  <<<dim3(HR, BB), 256>>>(b_o, 1);
    k_trans_full<<<dim3(HH, BB), 256>>>(b_o);
    k_bnorm     <<<BB, 1024>>>();
    k_valid_scan<<<BB, 1024>>>(mask_o);
    k_conv_planes<<<BB * LL * CC / 256, 256>>>();
    k_biTc      <<<dim3(9, BB), 128>>>();
    // GEMM1 (reduced): G = bt * ft^T (K=128) -> g_Sf
    k_mma       <<<dim3(8, 8, BB), 256, K_MMA_SMEM>>>(0);
    // sparse fused-S: only V valid rows, 81-tap gather from G -> compact Sv
    k_fused_sparse<<<dim3(4, 64, BB), 256>>>();
    // sparse softmax: reads compact Sv, writes compact score^T planes
    k_softmax_c <<<dim3(8, BB), 128>>>();
    // GEMM2 (sparse K): R[q][k'] = sum_vi scoreC[q][vi] * biC[k'][vi] -> g_R
    k_mma       <<<dim3(9, 8, BB), 256, K_MMA_SMEM>>>(1);
    k_out       <<<dim3(HH, BB), CC>>>(out);
}

// round 16
// speedup vs baseline: 9.2859x; 1.0061x over previous
#include <cuda_runtime.h>
#include <cuda_bf16.h>
#include <math.h>
#include <stdint.h>

// Problem constants
#define BB   16
#define CC   128
#define HH   64
#define WW   64
#define HR   32
#define WR   32
#define LL   1024          // HR*WR
#define KK   1152          // CC*9

// ---------------- scratch (device globals; only referenced from device code) --
__device__ float g_ft  [BB * HR * WR * CC];
__device__ float g_bt  [BB * HR * WR * CC];
__device__ float g_bot [BB * HH * WW * CC];
__device__ float g_ssq [BB * LL];
__device__ float g_bnorm[BB * LL];
__device__ int   g_plist[BB * LL];                   // compact valid-p lists
__device__ int   g_vcount[BB];                       // valid counts per batch
__device__ int   g_rowlist[BB * LL];                 // compact needed-G-row lists
__device__ int   g_rowmap [BB * LL];                 // u -> compact index (or -1)
__device__ int   g_rcount[BB];
__device__ float g_S  [BB * LL * LL];                // compact fused Sv [b][vi][q]
__device__ float g_Sf [BB * LL * LL];                // compact Gc [b][r][v]
__device__ float g_R  [BB * LL * KK];                // fp32 compact score [b][vi][q]
// bf16 split operand planes (GEMM1 only)
__device__ __nv_bfloat16 g_A1h[BB * LL * CC];        // gathered bt rows hi [b][r][c]
__device__ __nv_bfloat16 g_A1l[BB * LL * CC];        // gathered bt rows lo
__device__ __nv_bfloat16 g_B1h[BB * LL * CC];        // ft hi   [b][v][c]
__device__ __nv_bfloat16 g_B1l[BB * LL * CC];        // ft lo

// ---------------- PTX helpers (all baseline sm_80+, legal on compute_103) ----
__device__ __forceinline__ uint32_t smem_u32(const void* p) {
    uint32_t a;
    asm("{ .reg .u64 t; cvta.to.shared.u64 t, %1; cvt.u32.u64 %0, t; }" : "=r"(a) : "l"(p));
    return a;
}

#define CP_ASYNC16(dst, src) \
    asm volatile("cp.async.cg.shared.global [%0], [%1], 16;" :: "r"(dst), "l"(src))
#define CP_COMMIT() asm volatile("cp.async.commit_group;" ::: "memory")
#define CP_WAIT(n)  asm volatile("cp.async.wait_group %0;" :: "n"(n) : "memory")

#define LDSM_X4(r0, r1, r2, r3, addr) \
    asm volatile("ldmatrix.sync.aligned.m8n8.x4.shared.b16 {%0,%1,%2,%3}, [%4];" \
        : "=r"(r0), "=r"(r1), "=r"(r2), "=r"(r3) : "r"(addr))

#define MMA_BF16(c, a, b0, b1) \
    asm volatile("mma.sync.aligned.m16n8k16.row.col.f32.bf16.bf16.f32 " \
        "{%0,%1,%2,%3}, {%4,%5,%6,%7}, {%8,%9}, {%0,%1,%2,%3};" \
        : "+f"((c)[0]), "+f"((c)[1]), "+f"((c)[2]), "+f"((c)[3]) \
        : "r"((a)[0]), "r"((a)[1]), "r"((a)[2]), "r"((a)[3]), "r"(b0), "r"(b1))

__device__ __forceinline__ int tsw(int x) { return ((x & 31) << 5) | (x >> 5); }

// ---------------- transpose to channel-last ----------------------------------
__global__ void k_trans_ds(const float* __restrict__ src, int sel) {
    __shared__ float stage[HR * 129];
    const int y = blockIdx.x;
    const int b = blockIdx.y;
    float* dst = sel ? g_bt : g_ft;
    const int tid = threadIdx.x;
    for (int i = tid; i < HR * CC; i += 256) {
        int x = i & 31;
        int c = i >> 5;
        stage[x * 129 + c] = src[(((size_t)b * CC + c) * HH + 2 * y) * WW + 2 * x];
    }
    __syncthreads();
    for (int i = tid; i < HR * CC; i += 256) {
        int c = i & 127;
        int x = i >> 7;
        dst[(((size_t)b * HR + y) * WR + x) * CC + c] = stage[x * 129 + c];
    }
}

__global__ void k_trans_full(const float* __restrict__ src) {
    __shared__ float stage[WW * 129];
    const int y = blockIdx.x;
    const int b = blockIdx.y;
    const int tid = threadIdx.x;
    for (int i = tid; i < WW * CC; i += 256) {
        int x = i & 63;
        int c = i >> 6;
        stage[x * 129 + c] = src[(((size_t)b * CC + c) * HH + y) * WW + x];
    }
    __syncthreads();
    for (int i = tid; i < WW * CC; i += 256) {
        int c = i & 127;
        int x = i >> 7;
        g_bot[(((size_t)b * HH + y) * WW + x) * CC + c] = stage[x * 129 + c];
    }
}

// ---------------- bnorm: phase A (channel sum-of-squares, full-chip grid) -----
__global__ void k_bnorm_a() {
    const int b = blockIdx.y;
    const int warp = threadIdx.x >> 5, lane = threadIdx.x & 31;
    const int pos = blockIdx.x * 8 + warp;
    float4 v = *(const float4*)&g_bt[((size_t)b * LL + pos) * CC + lane * 4];
    float s = v.x * v.x + v.y * v.y + v.z * v.z + v.w * v.w;
    #pragma unroll
    for (int o = 16; o; o >>= 1) s += __shfl_xor_sync(0xffffffffu, s, o);
    if (lane == 0) g_ssq[b * LL + pos] = s;
}

// ---------------- bnorm: phase B (3x3 window + sqrt) --------------------------
__global__ void k_bnorm_b() {
    __shared__ float ss[LL];
    const int b = blockIdx.x;
    const int tid = threadIdx.x;
    ss[tid] = g_ssq[b * LL + tid];
    __syncthreads();
    const int py = tid >> 5, px = tid & 31;
    float sum = 0.f;
    #pragma unroll
    for (int i = 0; i < 3; i++)
        #pragma unroll
        for (int j = 0; j < 3; j++) {
            int y = py + i - 1, x = px + j - 1;
            if ((unsigned)y < HR && (unsigned)x < WR) sum += ss[y * WR + x];
        }
    g_bnorm[b * LL + tid] = fmaxf(sqrtf(sum), 1e-4f);
}

// ---------------- valid mask -> deterministic compact list --------------------
__global__ void k_valid_scan(const float* __restrict__ mask_o) {
    __shared__ float md[LL];
    __shared__ int sc[LL];
    const int b = blockIdx.x;
    const int tid = threadIdx.x;
    md[tid] = mask_o[(size_t)b * HH * WW + (2 * (tid >> 5)) * WW + 2 * (tid & 31)];
    __syncthreads();
    const int py = tid >> 5, px = tid & 31;
    float sum = 0.f;
    #pragma unroll
    for (int i = 0; i < 3; i++)
        #pragma unroll
        for (int j = 0; j < 3; j++) {
            int y = py + i - 1, x = px + j - 1;
            if ((unsigned)y < HR && (unsigned)x < WR) sum += md[y * WR + x];
        }
    const int flag = (sum == 0.f) ? 1 : 0;
    sc[tid] = flag;
    __syncthreads();
    for (int off = 1; off < LL; off <<= 1) {
        int v = sc[tid];
        if (tid >= off) v += sc[tid - off];
        __syncthreads();
        sc[tid] = v;
        __syncthreads();
    }
    if (flag) g_plist[b * LL + sc[tid] - 1] = tid;
    if (tid == LL - 1) g_vcount[b] = sc[LL - 1];
}

// ---------------- mark + compact the G rows needed by the fused gather --------
__global__ void k_rowmark() {
    __shared__ int flags[LL];
    __shared__ int sc[LL];
    const int b = blockIdx.x;
    const int tid = threadIdx.x;
    const int V = g_vcount[b];
    flags[tid] = 0;
    __syncthreads();
    for (int idx = tid; idx < V * 9; idx += LL) {
        const int vi = idx / 9, dd = idx % 9;
        const int d2 = dd / 3 - 1, d1 = dd % 3 - 1;
        const int p = g_plist[b * LL + vi];
        const int s = tsw(p) + d2;
        if ((unsigned)s >= LL) continue;
        const int A0 = tsw(s) + d1;
        if ((unsigned)A0 >= LL) continue;
        const int Ay = A0 >> 5, Ax = A0 & 31;
        for (int di = -1; di <= 1; di++) {
            if ((unsigned)(Ay + di) >= HR) continue;
            for (int dj = -1; dj <= 1; dj++) {
                if ((unsigned)(Ax + dj) >= WR) continue;
                atomicExch(&flags[A0 + di * 32 + dj], 1);
            }
        }
    }
    __syncthreads();
    sc[tid] = flags[tid];
    __syncthreads();
    for (int off = 1; off < LL; off <<= 1) {
        int v = sc[tid];
        if (tid >= off) v += sc[tid - off];
        __syncthreads();
        sc[tid] = v;
        __syncthreads();
    }
    if (flags[tid]) g_rowlist[b * LL + sc[tid] - 1] = tid;
    g_rowmap[b * LL + tid] = flags[tid] ? (sc[tid] - 1) : -1;
    if (tid == LL - 1) g_rcount[b] = sc[LL - 1];
}

// ---------------- bf16 hi/lo planes of ft (GEMM1 B operand) -------------------
__global__ void k_conv_planes() {
    const size_t i = (size_t)blockIdx.x * 256 + threadIdx.x;   // over BB*LL*CC
    const float fv = g_ft[i];
    __nv_bfloat16 h = __float2bfloat16(fv);
    g_B1h[i] = h;
    g_B1l[i] = __float2bfloat16(fv - __bfloat162float(h));
}

// ---------------- gather needed bt rows into compact A planes -----------------
__global__ void k_gatherA() {
    const int b = blockIdx.y;
    const int c = threadIdx.x;     // 128
    const int rcount = g_rcount[b];
    const int Rceil = (rcount + 127) & ~127;
    for (int r = blockIdx.x; r < Rceil; r += 8) {
        float v = 0.f;
        if (r < rcount) {
            const int row = g_rowlist[b * LL + r];
            v = g_bt[((size_t)b * LL + row) * CC + c];
        }
        const size_t o = ((size_t)b * LL + r) * CC + c;
        __nv_bfloat16 h = __float2bfloat16(v);
        g_A1h[o] = h;
        g_A1l[o] = __float2bfloat16(v - __bfloat162float(h));
    }
}

// ---------------- mma.sync split-bf16 GEMM1 (row-pruned) ----------------------
// Gc[r][v] = sum_c btg[r][c]*ft[v][c]   (M=Rceil dyn, N=1024, K=128) -> g_Sf
#define SM_STRIDE 40                 // padded bf16 elems per smem row
#define TILE_BYTES (128 * SM_STRIDE * 2)   // 10240
#define STAGE_BYTES (4 * TILE_BYTES)       // Ah, Al, Bh, Bl
#define K_MMA_SMEM (2 * STAGE_BYTES)       // 81920

__global__ void __launch_bounds__(256) k_mma1() {
    extern __shared__ __align__(16) char smem[];
    const uint32_t sbase = smem_u32(smem);
    const int tid = threadIdx.x;
    const int lane = tid & 31, wid = tid >> 5;
    const int wm = (wid & 3) * 32;
    const int wn = (wid >> 2) * 64;
    const int b = blockIdx.z, my = blockIdx.y, nx = blockIdx.x;

    const int rcount = g_rcount[b];
    const int Mceil = (rcount + 127) & ~127;
    if (my * 128 >= Mceil) return;

    const __nv_bfloat16* Ah = g_A1h + (size_t)b * LL * CC;
    const __nv_bfloat16* Al = g_A1l + (size_t)b * LL * CC;
    const __nv_bfloat16* Bh = g_B1h + (size_t)b * LL * CC;
    const __nv_bfloat16* Bl = g_B1l + (size_t)b * LL * CC;
    float* Cb = g_Sf + ((size_t)b << 20);

    float acc[2][8][4];
    #pragma unroll
    for (int mt = 0; mt < 2; mt++)
        #pragma unroll
        for (int nt = 0; nt < 8; nt++)
            #pragma unroll
            for (int u = 0; u < 4; u++) acc[mt][nt][u] = 0.f;

    auto load_stage = [&](int kt, int buf) {
        const uint32_t sdst = sbase + buf * STAGE_BYTES;
        #pragma unroll
        for (int t = 0; t < 4; t++) {
            const __nv_bfloat16* src = (t == 0) ? Ah : (t == 1) ? Al : (t == 2) ? Bh : Bl;
            const int rowbase = (t < 2) ? my * 128 : nx * 128;
            #pragma unroll
            for (int u = 0; u < 2; u++) {
                const int id = tid * 2 + u;
                const int r = id >> 2, c4 = id & 3;
                const uint32_t d = sdst + t * TILE_BYTES + (r * SM_STRIDE + c4 * 8) * 2;
                const __nv_bfloat16* s = src + (size_t)(rowbase + r) * CC + kt + c4 * 8;
                CP_ASYNC16(d, s);
            }
        }
        CP_COMMIT();
    };

    const int iters = CC / 32;   // 4
    load_stage(0, 0);

    for (int i = 0; i < iters; i++) {
        const int buf = i & 1;
        if (i + 1 < iters) load_stage((i + 1) * 32, buf ^ 1);
        if (i + 1 < iters) { CP_WAIT(1); } else { CP_WAIT(0); }
        __syncthreads();

        const uint32_t sa = sbase + buf * STAGE_BYTES;
        const uint32_t pAh = sa, pAl = sa + TILE_BYTES;
        const uint32_t pBh = sa + 2 * TILE_BYTES, pBl = sa + 3 * TILE_BYTES;

        #pragma unroll
        for (int ks = 0; ks < 2; ks++) {
            uint32_t ah[2][4], al[2][4];
            #pragma unroll
            for (int mt = 0; mt < 2; mt++) {
                const int r = wm + mt * 16 + (lane & 15);
                const uint32_t off = (uint32_t)(r * SM_STRIDE + ks * 16 + ((lane >> 4) << 3)) * 2;
                LDSM_X4(ah[mt][0], ah[mt][1], ah[mt][2], ah[mt][3], pAh + off);
                LDSM_X4(al[mt][0], al[mt][1], al[mt][2], al[mt][3], pAl + off);
            }
            #pragma unroll
            for (int np = 0; np < 4; np++) {
                const int rn = wn + np * 16 + (lane & 7) + ((lane >> 4) << 3);
                const uint32_t off = (uint32_t)(rn * SM_STRIDE + ks * 16 + (((lane >> 3) & 1) << 3)) * 2;
                uint32_t bh4[4], bl4[4];
                LDSM_X4(bh4[0], bh4[1], bh4[2], bh4[3], pBh + off);
                LDSM_X4(bl4[0], bl4[1], bl4[2], bl4[3], pBl + off);
                #pragma unroll
                for (int h2 = 0; h2 < 2; h2++) {
                    const int nt = np * 2 + h2;
                    #pragma unroll
                    for (int mt = 0; mt < 2; mt++) {
                        MMA_BF16(acc[mt][nt], ah[mt], bh4[h2 * 2], bh4[h2 * 2 + 1]);
                        MMA_BF16(acc[mt][nt], ah[mt], bl4[h2 * 2], bl4[h2 * 2 + 1]);
                        MMA_BF16(acc[mt][nt], al[mt], bh4[h2 * 2], bh4[h2 * 2 + 1]);
                    }
                }
            }
        }
        __syncthreads();
    }

    #pragma unroll
    for (int mt = 0; mt < 2; mt++) {
        const int row0 = my * 128 + wm + mt * 16 + (lane >> 2);
        #pragma unroll
        for (int nt = 0; nt < 8; nt++) {
            const int col = nx * 128 + wn + nt * 8 + (lane & 3) * 2;
            float* c0 = Cb + ((size_t)row0 << 10) + col;
            float* c1 = Cb + ((size_t)(row0 + 8) << 10) + col;
            c0[0] = acc[mt][nt][0]; c0[1] = acc[mt][nt][1];
            c1[0] = acc[mt][nt][2]; c1[1] = acc[mt][nt][3];
        }
    }
}

// ---------------- sparse fused-S gather (compact G rows) ----------------------
// fused[p][q] = sum_{d2} sum_{d1} Sraw[tsw(tsw(p)+d2)+d1][tsw(tsw(q)+d2)+d1]
// Sraw[A][C]  = (1/nrm_A) * sum_{di,dj} G[A+32di+dj][C+32di+dj]  (2D bounds)
__global__ void k_fused_sparse() {
    const int b = blockIdx.z;
    const int V = g_vcount[b];
    const int q = blockIdx.x * 256 + threadIdx.x;
    const float* Gc = g_Sf + ((size_t)b << 20);
    const int* rowmap = g_rowmap + b * LL;
    float* Sv = g_S + ((size_t)b << 20);
    const int tq = tsw(q);
    for (int vi = blockIdx.y; vi < V; vi += 64) {
        const int p = g_plist[b * LL + vi];
        const int tp = tsw(p);
        float acc = 0.f;
        #pragma unroll
        for (int d2 = -1; d2 <= 1; d2++) {
            const int s = tp + d2, t = tq + d2;
            if ((unsigned)s >= LL || (unsigned)t >= LL) continue;
            const int ss_ = tsw(s), tt = tsw(t);
            #pragma unroll
            for (int d1 = -1; d1 <= 1; d1++) {
                const int A = ss_ + d1, C = tt + d1;
                if ((unsigned)A >= LL || (unsigned)C >= LL) continue;
                const float inv = 1.f / g_bnorm[b * LL + A];
                const int Ay = A >> 5, Ax = A & 31, Cy = C >> 5, Cx = C & 31;
                float sub = 0.f;
                #pragma unroll
                for (int di = -1; di <= 1; di++) {
                    if ((unsigned)(Ay + di) >= HR || (unsigned)(Cy + di) >= HR) continue;
                    #pragma unroll
                    for (int dj = -1; dj <= 1; dj++) {
                        if ((unsigned)(Ax + dj) >= WR || (unsigned)(Cx + dj) >= WR) continue;
                        const int sh = di * 32 + dj;
                        sub += Gc[((size_t)rowmap[A + sh] << 10) + (C + sh)];
                    }
                }
                acc += inv * sub;
            }
        }
        Sv[((size_t)vi << 10) + q] = acc;
    }
}

// ---------------- sparse softmax; writes fp32 compact score [b][vi][q] --------
__global__ void k_softmax_c() {
    const int qt = blockIdx.x;     // 0..7
    const int b  = blockIdx.y;
    const int q  = qt * 128 + threadIdx.x;
    const int V = g_vcount[b];
    const float* Sv = g_S + ((size_t)b << 20);
    float* Sc = g_R + ((size_t)b << 20);
    float mx = (V < LL) ? 0.f : -1e30f;
    for (int vi = 0; vi < V; vi++)
        mx = fmaxf(mx, 10.f * Sv[((size_t)vi << 10) + q]);
    float sum = (V < LL) ? (float)(LL - V) * expf(0.f - mx) : 0.f;
    for (int vi = 0; vi < V; vi++)
        sum += expf(10.f * Sv[((size_t)vi << 10) + q] - mx);
    const float inv = 1.f / sum;
    for (int vi = 0; vi < V; vi++)
        Sc[((size_t)vi << 10) + q] = expf(10.f * Sv[((size_t)vi << 10) + q] - mx) * inv;
}

// ---------------- fused transposed-conv output (direct sparse aggregation) ----
// out[y,x,c] = 1/4 * sum_{taps(qy,qx)} sum_vi score[vi][q] * bo[2pvy+i-1][2pvx+j-1][c]
#define VSTAGE 160
__global__ void k_outf(float* __restrict__ out) {
    __shared__ int spy[VSTAGE], spx[VSTAGE];
    __shared__ float ssc[VSTAGE * 64];         // 40 KB
    const int y = blockIdx.x;
    const int b = blockIdx.y;
    const int c = threadIdx.x;                 // 128
    const int V = g_vcount[b];
    const int qylo = (y - 1) < 0 ? 0 : (y - 1) >> 1;
    int qyhi = (y + 1) >> 1; if (qyhi > 31) qyhi = 31;
    const bool staged = (V <= VSTAGE);
    if (staged) {
        for (int vi = c; vi < V; vi += 128) {
            const int p = g_plist[b * LL + vi];
            spy[vi] = p >> 5; spx[vi] = p & 31;
        }
        for (int idx = c; idx < V * 64; idx += 128) {
            const int vi = idx >> 6, qq = idx & 63;
            const int qy = qylo + (qq >> 5), qx = qq & 31;
            float v = 0.f;
            if (qy <= qyhi)
                v = g_R[((size_t)b << 20) + ((size_t)vi << 10) + qy * 32 + qx];
            ssc[idx] = v;
        }
        __syncthreads();
    }
    for (int x = 0; x < WW; x++) {
        const int qxlo = (x - 1) < 0 ? 0 : (x - 1) >> 1;
        int qxhi = (x + 1) >> 1; if (qxhi > 31) qxhi = 31;
        float acc = 0.f;
        for (int qy = qylo; qy <= qyhi; qy++) {
            const int i = y - 2 * qy + 1;
            if (i < 0 || i > 2) continue;
            for (int qx = qxlo; qx <= qxhi; qx++) {
                const int j = x - 2 * qx + 1;
                if (j < 0 || j > 2) continue;
                if (staged) {
                    const int qq = ((qy - qylo) << 5) + qx;
                    for (int vi = 0; vi < V; vi++) {
                        const float s = ssc[(vi << 6) + qq];
                        const int yy = 2 * spy[vi] + i - 1, xx = 2 * spx[vi] + j - 1;
                        if ((unsigned)yy < HH && (unsigned)xx < WW)
                            acc += s * g_bot[(((size_t)b * HH + yy) * WW + xx) * CC + c];
                    }
                } else {
                    const int q = qy * 32 + qx;
                    for (int vi = 0; vi < V; vi++) {
                        const float s = g_R[((size_t)b << 20) + ((size_t)vi << 10) + q];
                        const int p = g_plist[b * LL + vi];
                        const int yy = 2 * (p >> 5) + i - 1, xx = 2 * (p & 31) + j - 1;
                        if ((unsigned)yy < HH && (unsigned)xx < WW)
                            acc += s * g_bot[(((size_t)b * HH + yy) * WW + xx) * CC + c];
                    }
                }
            }
        }
        out[(((size_t)b * CC + c) * HH + y) * WW + x] = acc * 0.25f;
    }
}

// ---------------- orchestration ----------------------------------------------
extern "C" void kernel_launch(void* const* d_in, const int* in_sizes, int n_in,
                              void* d_out, int out_size) {
    const float* big[2] = {nullptr, nullptr};
    const float* mask_o = nullptr;
    int nb = 0;
    for (int i = 0; i < n_in && i < 3; i++) {
        if (in_sizes[i] == BB * 1 * HH * WW) {
            mask_o = (const float*)d_in[i];
        } else if (nb < 2) {
            big[nb++] = (const float*)d_in[i];
        }
    }
    const float* f_o = big[0] ? big[0] : (const float*)d_in[0];
    const float* b_o = big[1] ? big[1] : (const float*)d_in[1];
    if (!mask_o) mask_o = (const float*)d_in[2];
    float* out = (float*)d_out;

    cudaFuncSetAttribute(k_mma1, cudaFuncAttributeMaxDynamicSharedMemorySize, K_MMA_SMEM);

    k_trans_ds  <<<dim3(HR, BB), 256>>>(f_o, 0);
    k_trans_ds  <<<dim3(HR, BB), 256>>>(b_o, 1);
    k_trans_full<<<dim3(HH, BB), 256>>>(b_o);
    k_bnorm_a   <<<dim3(LL / 8, BB), 256>>>();
    k_bnorm_b   <<<BB, 1024>>>();
    k_valid_scan<<<BB, 1024>>>(mask_o);
    k_rowmark   <<<BB, 1024>>>();
    k_conv_planes<<<BB * LL * CC / 256, 256>>>();
    k_gatherA   <<<dim3(8, BB), 128>>>();
    // GEMM1 (row-pruned): Gc = btg * ft^T (K=128) -> g_Sf
    k_mma1      <<<dim3(8, 8, BB), 256, K_MMA_SMEM>>>();
    // sparse fused-S: V valid rows, 81-tap gather via rowmap -> compact Sv
    k_fused_sparse<<<dim3(4, 64, BB), 256>>>();
    // sparse softmax -> fp32 compact score (g_R)
    k_softmax_c <<<dim3(8, BB), 128>>>();
    // fused transposed-conv output (replaces GEMM2 + R + k_out)
    k_outf      <<<dim3(HH, BB), 128>>>(out);
}

// round 17
// speedup vs baseline: 11.9706x; 1.2891x over previous
#include <cuda_runtime.h>
#include <cuda_bf16.h>
#include <math.h>
#include <stdint.h>

// Problem constants
#define BB   16
#define CC   128
#define HH   64
#define WW   64
#define HR   32
#define WR   32
#define LL   1024          // HR*WR
#define KK   1152          // CC*9

// ---------------- scratch (device globals; only referenced from device code) --
__device__ float g_bt  [BB * HR * WR * CC];
__device__ float g_bot [BB * HH * WW * CC];
__device__ float g_ssq [BB * LL];
__device__ float g_bnorm[BB * LL];
__device__ int   g_plist[BB * LL];                   // compact valid-p lists
__device__ int   g_vcount[BB];                       // valid counts per batch
__device__ int   g_rowlist[BB * LL];                 // compact needed-G-row lists
__device__ int   g_rowmap [BB * LL];                 // u -> compact index (or -1)
__device__ int   g_rcount[BB];
__device__ float g_S  [BB * LL * LL];                // compact fused Sv [b][vi][q]
__device__ float g_Sf [BB * LL * LL];                // compact Gc [b][r][v]
__device__ float g_R  [BB * LL * KK];                // fp32 compact score [b][vi][q]
// bf16 split operand planes (GEMM1 only)
__device__ __nv_bfloat16 g_A1h[BB * LL * CC];        // gathered bt rows hi [b][r][c]
__device__ __nv_bfloat16 g_A1l[BB * LL * CC];        // gathered bt rows lo
__device__ __nv_bfloat16 g_B1h[BB * LL * CC];        // ft hi   [b][v][c]
__device__ __nv_bfloat16 g_B1l[BB * LL * CC];        // ft lo

// ---------------- PTX helpers (all baseline sm_80+, legal on compute_103) ----
__device__ __forceinline__ uint32_t smem_u32(const void* p) {
    uint32_t a;
    asm("{ .reg .u64 t; cvta.to.shared.u64 t, %1; cvt.u32.u64 %0, t; }" : "=r"(a) : "l"(p));
    return a;
}

#define CP_ASYNC16(dst, src) \
    asm volatile("cp.async.cg.shared.global [%0], [%1], 16;" :: "r"(dst), "l"(src))
#define CP_COMMIT() asm volatile("cp.async.commit_group;" ::: "memory")
#define CP_WAIT(n)  asm volatile("cp.async.wait_group %0;" :: "n"(n) : "memory")

#define LDSM_X4(r0, r1, r2, r3, addr) \
    asm volatile("ldmatrix.sync.aligned.m8n8.x4.shared.b16 {%0,%1,%2,%3}, [%4];" \
        : "=r"(r0), "=r"(r1), "=r"(r2), "=r"(r3) : "r"(addr))

#define MMA_BF16(c, a, b0, b1) \
    asm volatile("mma.sync.aligned.m16n8k16.row.col.f32.bf16.bf16.f32 " \
        "{%0,%1,%2,%3}, {%4,%5,%6,%7}, {%8,%9}, {%0,%1,%2,%3};" \
        : "+f"((c)[0]), "+f"((c)[1]), "+f"((c)[2]), "+f"((c)[3]) \
        : "r"((a)[0]), "r"((a)[1]), "r"((a)[2]), "r"((a)[3]), "r"(b0), "r"(b1))

__device__ __forceinline__ int tsw(int x) { return ((x & 31) << 5) | (x >> 5); }

// ---------------- f transpose -> bf16 hi/lo planes directly -------------------
__global__ void k_trans_f(const float* __restrict__ src) {
    __shared__ float stage[HR * 129];   // [x][c]
    const int y = blockIdx.x;
    const int b = blockIdx.y;
    const int tid = threadIdx.x;
    for (int i = tid; i < HR * CC; i += 256) {
        int x = i & 31;
        int c = i >> 5;
        stage[x * 129 + c] = src[(((size_t)b * CC + c) * HH + 2 * y) * WW + 2 * x];
    }
    __syncthreads();
    for (int i = tid; i < HR * CC; i += 256) {
        int c = i & 127;
        int x = i >> 7;
        const float v = stage[x * 129 + c];
        const size_t o = (((size_t)b * HR + y) * WR + x) * CC + c;
        __nv_bfloat16 h = __float2bfloat16(v);
        g_B1h[o] = h;
        g_B1l[o] = __float2bfloat16(v - __bfloat162float(h));
    }
}

// ---------------- b transpose -> g_bt + per-pixel channel sum-of-squares ------
__global__ void k_trans_b(const float* __restrict__ src) {
    __shared__ float stage[HR * 129];
    const int y = blockIdx.x;
    const int b = blockIdx.y;
    const int tid = threadIdx.x;
    const int warp = tid >> 5, lane = tid & 31;
    for (int i = tid; i < HR * CC; i += 256) {
        int x = i & 31;
        int c = i >> 5;
        stage[x * 129 + c] = src[(((size_t)b * CC + c) * HH + 2 * y) * WW + 2 * x];
    }
    __syncthreads();
    for (int i = tid; i < HR * CC; i += 256) {
        int c = i & 127;
        int x = i >> 7;
        g_bt[(((size_t)b * HR + y) * WR + x) * CC + c] = stage[x * 129 + c];
    }
    // ssq: 8 warps x 4 x-positions
    #pragma unroll
    for (int k = 0; k < 4; k++) {
        const int x = warp * 4 + k;
        float s = 0.f;
        #pragma unroll
        for (int cc = 0; cc < 4; cc++) {
            const float v = stage[x * 129 + lane + cc * 32];
            s += v * v;
        }
        #pragma unroll
        for (int o = 16; o; o >>= 1) s += __shfl_xor_sync(0xffffffffu, s, o);
        if (lane == 0) g_ssq[b * LL + y * WR + x] = s;
    }
}

// ---------------- full-res b transpose ----------------------------------------
__global__ void k_trans_full(const float* __restrict__ src) {
    __shared__ float stage[WW * 129];
    const int y = blockIdx.x;
    const int b = blockIdx.y;
    const int tid = threadIdx.x;
    for (int i = tid; i < WW * CC; i += 256) {
        int x = i & 63;
        int c = i >> 6;
        stage[x * 129 + c] = src[(((size_t)b * CC + c) * HH + y) * WW + x];
    }
    __syncthreads();
    for (int i = tid; i < WW * CC; i += 256) {
        int c = i & 127;
        int x = i >> 7;
        g_bot[(((size_t)b * HH + y) * WW + x) * CC + c] = stage[x * 129 + c];
    }
}

// ---------------- merged prep: bnorm window + valid scan + rowmark ------------
__global__ void k_prep(const float* __restrict__ mask_o) {
    __shared__ float fbuf[LL];
    __shared__ int flags[LL];
    __shared__ int sc[LL];
    __shared__ int sV;
    const int b = blockIdx.x;
    const int tid = threadIdx.x;
    const int py = tid >> 5, px = tid & 31;

    // --- bnorm: 3x3 window over ssq + sqrt ---
    fbuf[tid] = g_ssq[b * LL + tid];
    __syncthreads();
    {
        float sum = 0.f;
        #pragma unroll
        for (int i = 0; i < 3; i++)
            #pragma unroll
            for (int j = 0; j < 3; j++) {
                int y = py + i - 1, x = px + j - 1;
                if ((unsigned)y < HR && (unsigned)x < WR) sum += fbuf[y * WR + x];
            }
        g_bnorm[b * LL + tid] = fmaxf(sqrtf(sum), 1e-4f);
    }
    __syncthreads();

    // --- valid mask window + compact scan ---
    fbuf[tid] = mask_o[(size_t)b * HH * WW + (2 * py) * WW + 2 * px];
    __syncthreads();
    float msum = 0.f;
    #pragma unroll
    for (int i = 0; i < 3; i++)
        #pragma unroll
        for (int j = 0; j < 3; j++) {
            int y = py + i - 1, x = px + j - 1;
            if ((unsigned)y < HR && (unsigned)x < WR) msum += fbuf[y * WR + x];
        }
    const int vflag = (msum == 0.f) ? 1 : 0;
    sc[tid] = vflag;
    __syncthreads();
    for (int off = 1; off < LL; off <<= 1) {
        int v = sc[tid];
        if (tid >= off) v += sc[tid - off];
        __syncthreads();
        sc[tid] = v;
        __syncthreads();
    }
    if (vflag) g_plist[b * LL + sc[tid] - 1] = tid;
    if (tid == LL - 1) { g_vcount[b] = sc[LL - 1]; sV = sc[LL - 1]; }
    __syncthreads();
    const int V = sV;

    // --- rowmark: G rows needed by the fused gather ---
    flags[tid] = 0;
    __syncthreads();
    for (int idx = tid; idx < V * 9; idx += LL) {
        const int vi = idx / 9, dd = idx % 9;
        const int d2 = dd / 3 - 1, d1 = dd % 3 - 1;
        const int p = g_plist[b * LL + vi];
        const int s = tsw(p) + d2;
        if ((unsigned)s >= LL) continue;
        const int A0 = tsw(s) + d1;
        if ((unsigned)A0 >= LL) continue;
        const int Ay = A0 >> 5, Ax = A0 & 31;
        for (int di = -1; di <= 1; di++) {
            if ((unsigned)(Ay + di) >= HR) continue;
            for (int dj = -1; dj <= 1; dj++) {
                if ((unsigned)(Ax + dj) >= WR) continue;
                atomicExch(&flags[A0 + di * 32 + dj], 1);
            }
        }
    }
    __syncthreads();
    sc[tid] = flags[tid];
    __syncthreads();
    for (int off = 1; off < LL; off <<= 1) {
        int v = sc[tid];
        if (tid >= off) v += sc[tid - off];
        __syncthreads();
        sc[tid] = v;
        __syncthreads();
    }
    if (flags[tid]) g_rowlist[b * LL + sc[tid] - 1] = tid;
    g_rowmap[b * LL + tid] = flags[tid] ? (sc[tid] - 1) : -1;
    if (tid == LL - 1) g_rcount[b] = sc[LL - 1];
}

// ---------------- gather needed bt rows into compact A planes -----------------
__global__ void k_gatherA() {
    const int b = blockIdx.y;
    const int c = threadIdx.x;     // 128
    const int rcount = g_rcount[b];
    const int Rceil = (rcount + 127) & ~127;
    for (int r = blockIdx.x; r < Rceil; r += 8) {
        float v = 0.f;
        if (r < rcount) {
            const int row = g_rowlist[b * LL + r];
            v = g_bt[((size_t)b * LL + row) * CC + c];
        }
        const size_t o = ((size_t)b * LL + r) * CC + c;
        __nv_bfloat16 h = __float2bfloat16(v);
        g_A1h[o] = h;
        g_A1l[o] = __float2bfloat16(v - __bfloat162float(h));
    }
}

// ---------------- mma.sync split-bf16 GEMM1 (row-pruned) ----------------------
// Gc[r][v] = sum_c btg[r][c]*ft[v][c]   (M=Rceil dyn, N=1024, K=128) -> g_Sf
#define SM_STRIDE 40                 // padded bf16 elems per smem row
#define TILE_BYTES (128 * SM_STRIDE * 2)   // 10240
#define STAGE_BYTES (4 * TILE_BYTES)       // Ah, Al, Bh, Bl
#define K_MMA_SMEM (2 * STAGE_BYTES)       // 81920

__global__ void __launch_bounds__(256) k_mma1() {
    extern __shared__ __align__(16) char smem[];
    const uint32_t sbase = smem_u32(smem);
    const int tid = threadIdx.x;
    const int lane = tid & 31, wid = tid >> 5;
    const int wm = (wid & 3) * 32;
    const int wn = (wid >> 2) * 64;
    const int b = blockIdx.z, my = blockIdx.y, nx = blockIdx.x;

    const int rcount = g_rcount[b];
    const int Mceil = (rcount + 127) & ~127;
    if (my * 128 >= Mceil) return;

    const __nv_bfloat16* Ah = g_A1h + (size_t)b * LL * CC;
    const __nv_bfloat16* Al = g_A1l + (size_t)b * LL * CC;
    const __nv_bfloat16* Bh = g_B1h + (size_t)b * LL * CC;
    const __nv_bfloat16* Bl = g_B1l + (size_t)b * LL * CC;
    float* Cb = g_Sf + ((size_t)b << 20);

    float acc[2][8][4];
    #pragma unroll
    for (int mt = 0; mt < 2; mt++)
        #pragma unroll
        for (int nt = 0; nt < 8; nt++)
            #pragma unroll
            for (int u = 0; u < 4; u++) acc[mt][nt][u] = 0.f;

    auto load_stage = [&](int kt, int buf) {
        const uint32_t sdst = sbase + buf * STAGE_BYTES;
        #pragma unroll
        for (int t = 0; t < 4; t++) {
            const __nv_bfloat16* src = (t == 0) ? Ah : (t == 1) ? Al : (t == 2) ? Bh : Bl;
            const int rowbase = (t < 2) ? my * 128 : nx * 128;
            #pragma unroll
            for (int u = 0; u < 2; u++) {
                const int id = tid * 2 + u;
                const int r = id >> 2, c4 = id & 3;
                const uint32_t d = sdst + t * TILE_BYTES + (r * SM_STRIDE + c4 * 8) * 2;
                const __nv_bfloat16* s = src + (size_t)(rowbase + r) * CC + kt + c4 * 8;
                CP_ASYNC16(d, s);
            }
        }
        CP_COMMIT();
    };

    const int iters = CC / 32;   // 4
    load_stage(0, 0);

    for (int i = 0; i < iters; i++) {
        const int buf = i & 1;
        if (i + 1 < iters) load_stage((i + 1) * 32, buf ^ 1);
        if (i + 1 < iters) { CP_WAIT(1); } else { CP_WAIT(0); }
        __syncthreads();

        const uint32_t sa = sbase + buf * STAGE_BYTES;
        const uint32_t pAh = sa, pAl = sa + TILE_BYTES;
        const uint32_t pBh = sa + 2 * TILE_BYTES, pBl = sa + 3 * TILE_BYTES;

        #pragma unroll
        for (int ks = 0; ks < 2; ks++) {
            uint32_t ah[2][4], al[2][4];
            #pragma unroll
            for (int mt = 0; mt < 2; mt++) {
                const int r = wm + mt * 16 + (lane & 15);
                const uint32_t off = (uint32_t)(r * SM_STRIDE + ks * 16 + ((lane >> 4) << 3)) * 2;
                LDSM_X4(ah[mt][0], ah[mt][1], ah[mt][2], ah[mt][3], pAh + off);
                LDSM_X4(al[mt][0], al[mt][1], al[mt][2], al[mt][3], pAl + off);
            }
            #pragma unroll
            for (int np = 0; np < 4; np++) {
                const int rn = wn + np * 16 + (lane & 7) + ((lane >> 4) << 3);
                const uint32_t off = (uint32_t)(rn * SM_STRIDE + ks * 16 + (((lane >> 3) & 1) << 3)) * 2;
                uint32_t bh4[4], bl4[4];
                LDSM_X4(bh4[0], bh4[1], bh4[2], bh4[3], pBh + off);
                LDSM_X4(bl4[0], bl4[1], bl4[2], bl4[3], pBl + off);
                #pragma unroll
                for (int h2 = 0; h2 < 2; h2++) {
                    const int nt = np * 2 + h2;
                    #pragma unroll
                    for (int mt = 0; mt < 2; mt++) {
                        MMA_BF16(acc[mt][nt], ah[mt], bh4[h2 * 2], bh4[h2 * 2 + 1]);
                        MMA_BF16(acc[mt][nt], ah[mt], bl4[h2 * 2], bl4[h2 * 2 + 1]);
                        MMA_BF16(acc[mt][nt], al[mt], bh4[h2 * 2], bh4[h2 * 2 + 1]);
                    }
                }
            }
        }
        __syncthreads();
    }

    #pragma unroll
    for (int mt = 0; mt < 2; mt++) {
        const int row0 = my * 128 + wm + mt * 16 + (lane >> 2);
        #pragma unroll
        for (int nt = 0; nt < 8; nt++) {
            const int col = nx * 128 + wn + nt * 8 + (lane & 3) * 2;
            float* c0 = Cb + ((size_t)row0 << 10) + col;
            float* c1 = Cb + ((size_t)(row0 + 8) << 10) + col;
            c0[0] = acc[mt][nt][0]; c0[1] = acc[mt][nt][1];
            c1[0] = acc[mt][nt][2]; c1[1] = acc[mt][nt][3];
        }
    }
}

// ---------------- sparse fused-S gather (compact G rows) ----------------------
__global__ void k_fused_sparse() {
    const int b = blockIdx.z;
    const int V = g_vcount[b];
    const int q = blockIdx.x * 256 + threadIdx.x;
    const float* Gc = g_Sf + ((size_t)b << 20);
    const int* rowmap = g_rowmap + b * LL;
    float* Sv = g_S + ((size_t)b << 20);
    const int tq = tsw(q);
    for (int vi = blockIdx.y; vi < V; vi += 64) {
        const int p = g_plist[b * LL + vi];
        const int tp = tsw(p);
        float acc = 0.f;
        #pragma unroll
        for (int d2 = -1; d2 <= 1; d2++) {
            const int s = tp + d2, t = tq + d2;
            if ((unsigned)s >= LL || (unsigned)t >= LL) continue;
            const int ss_ = tsw(s), tt = tsw(t);
            #pragma unroll
            for (int d1 = -1; d1 <= 1; d1++) {
                const int A = ss_ + d1, C = tt + d1;
                if ((unsigned)A >= LL || (unsigned)C >= LL) continue;
                const float inv = 1.f / g_bnorm[b * LL + A];
                const int Ay = A >> 5, Ax = A & 31, Cy = C >> 5, Cx = C & 31;
                float sub = 0.f;
                #pragma unroll
                for (int di = -1; di <= 1; di++) {
                    if ((unsigned)(Ay + di) >= HR || (unsigned)(Cy + di) >= HR) continue;
                    #pragma unroll
                    for (int dj = -1; dj <= 1; dj++) {
                        if ((unsigned)(Ax + dj) >= WR || (unsigned)(Cx + dj) >= WR) continue;
                        const int sh = di * 32 + dj;
                        sub += Gc[((size_t)rowmap[A + sh] << 10) + (C + sh)];
                    }
                }
                acc += inv * sub;
            }
        }
        Sv[((size_t)vi << 10) + q] = acc;
    }
}

// ---------------- sparse softmax; writes fp32 compact score [b][vi][q] --------
__global__ void k_softmax_c() {
    const int qt = blockIdx.x;     // 0..7
    const int b  = blockIdx.y;
    const int q  = qt * 128 + threadIdx.x;
    const int V = g_vcount[b];
    const float* Sv = g_S + ((size_t)b << 20);
    float* Sc = g_R + ((size_t)b << 20);
    float mx = (V < LL) ? 0.f : -1e30f;
    for (int vi = 0; vi < V; vi++)
        mx = fmaxf(mx, 10.f * Sv[((size_t)vi << 10) + q]);
    float sum = (V < LL) ? (float)(LL - V) * expf(0.f - mx) : 0.f;
    for (int vi = 0; vi < V; vi++)
        sum += expf(10.f * Sv[((size_t)vi << 10) + q] - mx);
    const float inv = 1.f / sum;
    for (int vi = 0; vi < V; vi++)
        Sc[((size_t)vi << 10) + q] = expf(10.f * Sv[((size_t)vi << 10) + q] - mx) * inv;
}

// ---------------- fused transposed-conv output (x-sliced for parallelism) -----
// out[y,x,c] = 1/4 * sum_{taps(qy,qx)} sum_vi score[vi][q] * bo[2pvy+i-1][2pvx+j-1][c]
#define VSTAGE 160
__global__ void k_outf(float* __restrict__ out) {
    __shared__ int spy[VSTAGE], spx[VSTAGE];
    __shared__ float ssc[VSTAGE * 64];         // 40 KB
    const int y = blockIdx.x;
    const int xg = blockIdx.y;                 // 0..3, 16-wide x slice
    const int b = blockIdx.z;
    const int c = threadIdx.x;                 // 128
    const int V = g_vcount[b];
    const int qylo = (y - 1) < 0 ? 0 : (y - 1) >> 1;
    int qyhi = (y + 1) >> 1; if (qyhi > 31) qyhi = 31;
    const bool staged = (V <= VSTAGE);
    if (staged) {
        for (int vi = c; vi < V; vi += 128) {
            const int p = g_plist[b * LL + vi];
            spy[vi] = p >> 5; spx[vi] = p & 31;
        }
        for (int idx = c; idx < V * 64; idx += 128) {
            const int vi = idx >> 6, qq = idx & 63;
            const int qy = qylo + (qq >> 5), qx = qq & 31;
            float v = 0.f;
            if (qy <= qyhi)
                v = g_R[((size_t)b << 20) + ((size_t)vi << 10) + qy * 32 + qx];
            ssc[idx] = v;
        }
        __syncthreads();
    }
    for (int x = xg * 16; x < xg * 16 + 16; x++) {
        const int qxlo = (x - 1) < 0 ? 0 : (x - 1) >> 1;
        int qxhi = (x + 1) >> 1; if (qxhi > 31) qxhi = 31;
        float acc = 0.f;
        for (int qy = qylo; qy <= qyhi; qy++) {
            const int i = y - 2 * qy + 1;
            if (i < 0 || i > 2) continue;
            for (int qx = qxlo; qx <= qxhi; qx++) {
                const int j = x - 2 * qx + 1;
                if (j < 0 || j > 2) continue;
                if (staged) {
                    const int qq = ((qy - qylo) << 5) + qx;
                    for (int vi = 0; vi < V; vi++) {
                        const float s = ssc[(vi << 6) + qq];
                        const int yy = 2 * spy[vi] + i - 1, xx = 2 * spx[vi] + j - 1;
                        if ((unsigned)yy < HH && (unsigned)xx < WW)
                            acc += s * g_bot[(((size_t)b * HH + yy) * WW + xx) * CC + c];
                    }
                } else {
                    const int q = qy * 32 + qx;
                    for (int vi = 0; vi < V; vi++) {
                        const float s = g_R[((size_t)b << 20) + ((size_t)vi << 10) + q];
                        const int p = g_plist[b * LL + vi];
                        const int yy = 2 * (p >> 5) + i - 1, xx = 2 * (p & 31) + j - 1;
                        if ((unsigned)yy < HH && (unsigned)xx < WW)
                            acc += s * g_bot[(((size_t)b * HH + yy) * WW + xx) * CC + c];
                    }
                }
            }
        }
        out[(((size_t)b * CC + c) * HH + y) * WW + x] = acc * 0.25f;
    }
}

// ---------------- orchestration ----------------------------------------------
extern "C" void kernel_launch(void* const* d_in, const int* in_sizes, int n_in,
                              void* d_out, int out_size) {
    const float* big[2] = {nullptr, nullptr};
    const float* mask_o = nullptr;
    int nb = 0;
    for (int i = 0; i < n_in && i < 3; i++) {
        if (in_sizes[i] == BB * 1 * HH * WW) {
            mask_o = (const float*)d_in[i];
        } else if (nb < 2) {
            big[nb++] = (const float*)d_in[i];
        }
    }
    const float* f_o = big[0] ? big[0] : (const float*)d_in[0];
    const float* b_o = big[1] ? big[1] : (const float*)d_in[1];
    if (!mask_o) mask_o = (const float*)d_in[2];
    float* out = (float*)d_out;

    cudaFuncSetAttribute(k_mma1, cudaFuncAttributeMaxDynamicSharedMemorySize, K_MMA_SMEM);

    k_trans_f   <<<dim3(HR, BB), 256>>>(f_o);
    k_trans_b   <<<dim3(HR, BB), 256>>>(b_o);
    k_trans_full<<<dim3(HH, BB), 256>>>(b_o);
    k_prep      <<<BB, 1024>>>(mask_o);
    k_gatherA   <<<dim3(8, BB), 128>>>();
    // GEMM1 (row-pruned): Gc = btg * ft^T (K=128) -> g_Sf
    k_mma1      <<<dim3(8, 8, BB), 256, K_MMA_SMEM>>>();
    // sparse fused-S: V valid rows, 81-tap gather via rowmap -> compact Sv
    k_fused_sparse<<<dim3(4, 64, BB), 256>>>();
    // sparse softmax -> fp32 compact score (g_R)
    k_softmax_c <<<dim3(8, BB), 128>>>();
    // fused transposed-conv output (x-sliced 4x for latency hiding)
    k_outf      <<<dim3(HH, 4, BB), 128>>>(out);
}